// round 1
// baseline (speedup 1.0000x reference)
#include <cuda_runtime.h>
#include <cuda_bf16.h>
#include <math.h>

// Problem constants
#define BATCH   2
#define SLEN    2048
#define DMODEL  1024
#define NHEADS  16
#define HEADDIM 64
#define NROWS   (BATCH * SLEN)      // 4096
#define NGROUPS (BATCH * NHEADS)    // 32 reshaped "heads"

// Scratch (allocation-free rule: __device__ globals)
__device__ float g_Q[NROWS * DMODEL];
__device__ float g_K[NROWS * DMODEL];
__device__ float g_V[NROWS * DMODEL];
__device__ float g_O[NROWS * DMODEL];
__device__ float g_P[NROWS * DMODEL];

// ---------------------------------------------------------------------------
// GEMM: C[M,N] = A[M,K] @ B[K,N] (+ bias[N] if bias != nullptr)
// 128x128 block tile, BK=8, 256 threads, 8x8 per-thread tile (split halves).
// ---------------------------------------------------------------------------
__global__ __launch_bounds__(256) void gemm_f32(
    const float* __restrict__ A, const float* __restrict__ B,
    const float* __restrict__ bias, float* __restrict__ C,
    int M, int N, int K)
{
    __shared__ float As[8][132];   // transposed A tile, padded (conflict-free)
    __shared__ float Bs[8][128];

    const int tid = threadIdx.x;
    const int tx = tid & 15;
    const int ty = tid >> 4;
    const int m0 = blockIdx.y * 128;
    const int n0 = blockIdx.x * 128;

    float acc[8][8];
#pragma unroll
    for (int i = 0; i < 8; i++)
#pragma unroll
        for (int j = 0; j < 8; j++) acc[i][j] = 0.f;

    const int ar = tid >> 1;           // 0..127
    const int ac = (tid & 1) * 4;      // 0 or 4
    const int br = tid >> 5;           // 0..7
    const int bc = (tid & 31) * 4;     // 0..124

    const float* Aptr = A + (size_t)(m0 + ar) * K + ac;
    const float* Bptr = B + (size_t)br * N + n0 + bc;

    for (int k0 = 0; k0 < K; k0 += 8) {
        float4 av = *(const float4*)(Aptr + k0);
        float4 bv = *(const float4*)(Bptr + (size_t)k0 * N);
        __syncthreads();   // previous iteration's reads complete
        As[ac + 0][ar] = av.x;
        As[ac + 1][ar] = av.y;
        As[ac + 2][ar] = av.z;
        As[ac + 3][ar] = av.w;
        *(float4*)&Bs[br][bc] = bv;
        __syncthreads();
#pragma unroll
        for (int kk = 0; kk < 8; kk++) {
            float4 a0 = *(const float4*)&As[kk][ty * 4];
            float4 a1 = *(const float4*)&As[kk][64 + ty * 4];
            float4 b0 = *(const float4*)&Bs[kk][tx * 4];
            float4 b1 = *(const float4*)&Bs[kk][64 + tx * 4];
            float a[8] = {a0.x, a0.y, a0.z, a0.w, a1.x, a1.y, a1.z, a1.w};
            float b[8] = {b0.x, b0.y, b0.z, b0.w, b1.x, b1.y, b1.z, b1.w};
#pragma unroll
            for (int i = 0; i < 8; i++)
#pragma unroll
                for (int j = 0; j < 8; j++) acc[i][j] += a[i] * b[j];
        }
    }

#pragma unroll
    for (int ih = 0; ih < 2; ih++) {
#pragma unroll
        for (int i = 0; i < 4; i++) {
            const int m = m0 + ih * 64 + ty * 4 + i;
#pragma unroll
            for (int jh = 0; jh < 2; jh++) {
                const int n = n0 + jh * 64 + tx * 4;
                float4 v;
                v.x = acc[ih * 4 + i][jh * 4 + 0];
                v.y = acc[ih * 4 + i][jh * 4 + 1];
                v.z = acc[ih * 4 + i][jh * 4 + 2];
                v.w = acc[ih * 4 + i][jh * 4 + 3];
                if (bias) {
                    v.x += bias[n + 0];
                    v.y += bias[n + 1];
                    v.z += bias[n + 2];
                    v.w += bias[n + 3];
                }
                *(float4*)(C + (size_t)m * N + n) = v;
            }
        }
    }
}

// ---------------------------------------------------------------------------
// Flash attention over reshaped heads: Q,K,V viewed as [32][2048][64].
// Block = (qb, g): 64 query rows. K/V tiles of 64. Online softmax.
// 256 threads: thread (ty,tx) owns 4x4 of the 64x64 score/O tile.
// Dyn smem: sQ[64*64] + sKT[64*68] + sPT[64*65] + sV[64*64] floats = 66816 B
// ---------------------------------------------------------------------------
__global__ __launch_bounds__(256) void attn_f32(
    const float* __restrict__ Q, const float* __restrict__ K,
    const float* __restrict__ V, const unsigned char* __restrict__ mask,
    float* __restrict__ O)
{
    extern __shared__ float sm[];
    float* sQ  = sm;                    // [64][64] row-major
    float* sKT = sQ + 64 * 64;          // [d=64][c=64] pad 68 (transposed K tile)
    float* sPT = sKT + 64 * 68;         // [k=64][r=64] pad 65 (transposed P tile)
    float* sV  = sPT + 64 * 65;         // [64][64] row-major

    const int tid = threadIdx.x;
    const int tx = tid & 15;
    const int ty = tid >> 4;
    const int qb = blockIdx.x;          // 0..31
    const int g  = blockIdx.y;          // 0..31

    const float* Qh = Q + ((size_t)g * SLEN + qb * 64) * HEADDIM;
    const float* Kh = K + (size_t)g * SLEN * HEADDIM;
    const float* Vh = V + (size_t)g * SLEN * HEADDIM;
    const unsigned char* mrow =
        mask + (size_t)(g & (BATCH - 1)) * SLEN * SLEN + (size_t)(qb * 64) * SLEN;

    // Load Q tile (row-major, coalesced). thread: row tid/4, 16 floats.
    {
        const int r = tid >> 2;
        const int c = (tid & 3) * 16;
#pragma unroll
        for (int u = 0; u < 4; u++) {
            float4 v = *(const float4*)(Qh + r * 64 + c + u * 4);
            *(float4*)&sQ[r * 64 + c + u * 4] = v;
        }
    }

    float mrun[4], lrun[4];
    float o[4][4];
#pragma unroll
    for (int i = 0; i < 4; i++) {
        mrun[i] = -INFINITY;
        lrun[i] = 0.f;
#pragma unroll
        for (int j = 0; j < 4; j++) o[i][j] = 0.f;
    }

    const float scale = 0.125f;  // 1/sqrt(64)

    for (int kt = 0; kt < SLEN / 64; kt++) {
        __syncthreads();   // previous P*V reads done before overwriting tiles
        // Load K tile transposed into sKT[d][c], V tile row-major into sV.
        {
            const int r = tid >> 2;           // seq row within tile (c index)
            const int c = (tid & 3) * 16;     // dim start
#pragma unroll
            for (int u = 0; u < 4; u++) {
                float4 kv = *(const float4*)(Kh + (size_t)(kt * 64 + r) * 64 + c + u * 4);
                sKT[(c + u * 4 + 0) * 68 + r] = kv.x;
                sKT[(c + u * 4 + 1) * 68 + r] = kv.y;
                sKT[(c + u * 4 + 2) * 68 + r] = kv.z;
                sKT[(c + u * 4 + 3) * 68 + r] = kv.w;
                float4 vv = *(const float4*)(Vh + (size_t)(kt * 64 + r) * 64 + c + u * 4);
                *(float4*)&sV[r * 64 + c + u * 4] = vv;
            }
        }
        __syncthreads();

        // Scores: S[r][c] = sum_d Q[r][d] * K[c][d]
        float sacc[4][4];
#pragma unroll
        for (int i = 0; i < 4; i++)
#pragma unroll
            for (int j = 0; j < 4; j++) sacc[i][j] = 0.f;

#pragma unroll 16
        for (int d = 0; d < 64; d++) {
            float4 bv = *(const float4*)&sKT[d * 68 + tx * 4];
            float a0 = sQ[(ty * 4 + 0) * 64 + d];
            float a1 = sQ[(ty * 4 + 1) * 64 + d];
            float a2 = sQ[(ty * 4 + 2) * 64 + d];
            float a3 = sQ[(ty * 4 + 3) * 64 + d];
            sacc[0][0] += a0 * bv.x; sacc[0][1] += a0 * bv.y; sacc[0][2] += a0 * bv.z; sacc[0][3] += a0 * bv.w;
            sacc[1][0] += a1 * bv.x; sacc[1][1] += a1 * bv.y; sacc[1][2] += a1 * bv.z; sacc[1][3] += a1 * bv.w;
            sacc[2][0] += a2 * bv.x; sacc[2][1] += a2 * bv.y; sacc[2][2] += a2 * bv.z; sacc[2][3] += a2 * bv.w;
            sacc[3][0] += a3 * bv.x; sacc[3][1] += a3 * bv.y; sacc[3][2] += a3 * bv.z; sacc[3][3] += a3 * bv.w;
        }

        // Mask, online softmax, stage P transposed.
#pragma unroll
        for (int i = 0; i < 4; i++) {
            uchar4 mk = *(const uchar4*)(mrow + (size_t)(ty * 4 + i) * SLEN + kt * 64 + tx * 4);
            float s0 = mk.x ? -1e9f : sacc[i][0] * scale;
            float s1 = mk.y ? -1e9f : sacc[i][1] * scale;
            float s2 = mk.z ? -1e9f : sacc[i][2] * scale;
            float s3 = mk.w ? -1e9f : sacc[i][3] * scale;

            float rmax = fmaxf(fmaxf(s0, s1), fmaxf(s2, s3));
#pragma unroll
            for (int off = 8; off >= 1; off >>= 1)
                rmax = fmaxf(rmax, __shfl_xor_sync(0xffffffffu, rmax, off));

            float mnew = fmaxf(mrun[i], rmax);
            float p0 = __expf(s0 - mnew);
            float p1 = __expf(s1 - mnew);
            float p2 = __expf(s2 - mnew);
            float p3 = __expf(s3 - mnew);
            float rsum = p0 + p1 + p2 + p3;
#pragma unroll
            for (int off = 8; off >= 1; off >>= 1)
                rsum += __shfl_xor_sync(0xffffffffu, rsum, off);

            float corr = __expf(mrun[i] - mnew);   // exp(-inf)=0 on first tile
            lrun[i] = lrun[i] * corr + rsum;
            mrun[i] = mnew;
            o[i][0] *= corr; o[i][1] *= corr; o[i][2] *= corr; o[i][3] *= corr;

            const int r = ty * 4 + i;
            sPT[(tx * 4 + 0) * 65 + r] = p0;
            sPT[(tx * 4 + 1) * 65 + r] = p1;
            sPT[(tx * 4 + 2) * 65 + r] = p2;
            sPT[(tx * 4 + 3) * 65 + r] = p3;
        }
        __syncthreads();

        // O += P * V
#pragma unroll 16
        for (int k = 0; k < 64; k++) {
            float4 bv = *(const float4*)&sV[k * 64 + tx * 4];
            float a0 = sPT[k * 65 + ty * 4 + 0];
            float a1 = sPT[k * 65 + ty * 4 + 1];
            float a2 = sPT[k * 65 + ty * 4 + 2];
            float a3 = sPT[k * 65 + ty * 4 + 3];
            o[0][0] += a0 * bv.x; o[0][1] += a0 * bv.y; o[0][2] += a0 * bv.z; o[0][3] += a0 * bv.w;
            o[1][0] += a1 * bv.x; o[1][1] += a1 * bv.y; o[1][2] += a1 * bv.z; o[1][3] += a1 * bv.w;
            o[2][0] += a2 * bv.x; o[2][1] += a2 * bv.y; o[2][2] += a2 * bv.z; o[2][3] += a2 * bv.w;
            o[3][0] += a3 * bv.x; o[3][1] += a3 * bv.y; o[3][2] += a3 * bv.z; o[3][3] += a3 * bv.w;
        }
    }

    // Normalize and write O (viewed as [32][2048][64] flat == [4096][1024])
#pragma unroll
    for (int i = 0; i < 4; i++) {
        float inv = 1.f / lrun[i];
        float4 v;
        v.x = o[i][0] * inv; v.y = o[i][1] * inv;
        v.z = o[i][2] * inv; v.w = o[i][3] * inv;
        size_t idx = ((size_t)g * SLEN + qb * 64 + ty * 4 + i) * HEADDIM + tx * 4;
        *(float4*)(O + idx) = v;
    }
}

// ---------------------------------------------------------------------------
// Fused residual + LayerNorm: out = LN(x + p) * gamma + beta, rows of 1024.
// ---------------------------------------------------------------------------
__global__ __launch_bounds__(256) void ln_kernel(
    const float* __restrict__ x, const float* __restrict__ p,
    const float* __restrict__ gamma, const float* __restrict__ beta,
    float* __restrict__ out)
{
    const int row = blockIdx.x;
    const int t = threadIdx.x;
    const size_t base = (size_t)row * DMODEL + t * 4;

    float4 xv = *(const float4*)(x + base);
    float4 pv = *(const float4*)(p + base);
    float v0 = xv.x + pv.x, v1 = xv.y + pv.y, v2 = xv.z + pv.z, v3 = xv.w + pv.w;

    __shared__ float red[8];
    float s = v0 + v1 + v2 + v3;
#pragma unroll
    for (int off = 16; off >= 1; off >>= 1) s += __shfl_xor_sync(0xffffffffu, s, off);
    if ((t & 31) == 0) red[t >> 5] = s;
    __syncthreads();
    float mu = (red[0] + red[1] + red[2] + red[3] +
                red[4] + red[5] + red[6] + red[7]) * (1.f / DMODEL);
    __syncthreads();

    float d0 = v0 - mu, d1 = v1 - mu, d2 = v2 - mu, d3 = v3 - mu;
    float q = d0 * d0 + d1 * d1 + d2 * d2 + d3 * d3;
#pragma unroll
    for (int off = 16; off >= 1; off >>= 1) q += __shfl_xor_sync(0xffffffffu, q, off);
    if ((t & 31) == 0) red[t >> 5] = q;
    __syncthreads();
    float var = (red[0] + red[1] + red[2] + red[3] +
                 red[4] + red[5] + red[6] + red[7]) * (1.f / DMODEL);
    float rs = rsqrtf(var + 1e-5f);

    float4 gv = *(const float4*)(gamma + t * 4);
    float4 bv = *(const float4*)(beta + t * 4);
    float4 ov;
    ov.x = d0 * rs * gv.x + bv.x;
    ov.y = d1 * rs * gv.y + bv.y;
    ov.z = d2 * rs * gv.z + bv.z;
    ov.w = d3 * rs * gv.w + bv.w;
    *(float4*)(out + base) = ov;
}

// ---------------------------------------------------------------------------
// Launch
// ---------------------------------------------------------------------------
extern "C" void kernel_launch(void* const* d_in, const int* in_sizes, int n_in,
                              void* d_out, int out_size)
{
    (void)in_sizes; (void)n_in; (void)out_size;
    const float* q_in  = (const float*)d_in[0];
    const float* k_in  = (const float*)d_in[1];
    const float* v_in  = (const float*)d_in[2];
    const unsigned char* mask = (const unsigned char*)d_in[3];
    const float* Wq = (const float*)d_in[4];
    const float* Wk = (const float*)d_in[5];
    const float* Wv = (const float*)d_in[6];
    const float* Wo = (const float*)d_in[7];
    const float* bo = (const float*)d_in[8];
    const float* gamma = (const float*)d_in[9];
    const float* beta  = (const float*)d_in[10];
    float* out = (float*)d_out;

    float *pQ, *pK, *pV, *pO, *pP;
    cudaGetSymbolAddress((void**)&pQ, g_Q);
    cudaGetSymbolAddress((void**)&pK, g_K);
    cudaGetSymbolAddress((void**)&pV, g_V);
    cudaGetSymbolAddress((void**)&pO, g_O);
    cudaGetSymbolAddress((void**)&pP, g_P);

    const int attn_smem = (64 * 64 + 64 * 68 + 64 * 65 + 64 * 64) * (int)sizeof(float);
    cudaFuncSetAttribute(attn_f32, cudaFuncAttributeMaxDynamicSharedMemorySize, attn_smem);

    dim3 ggrid(DMODEL / 128, NROWS / 128);   // (8, 32)
    gemm_f32<<<ggrid, 256>>>(q_in, Wq, nullptr, pQ, NROWS, DMODEL, DMODEL);
    gemm_f32<<<ggrid, 256>>>(k_in, Wk, nullptr, pK, NROWS, DMODEL, DMODEL);
    gemm_f32<<<ggrid, 256>>>(v_in, Wv, nullptr, pV, NROWS, DMODEL, DMODEL);

    dim3 agrid(SLEN / 64, NGROUPS);          // (32, 32)
    attn_f32<<<agrid, 256, attn_smem>>>(pQ, pK, pV, mask, pO);

    gemm_f32<<<ggrid, 256>>>(pO, Wo, bo, pP, NROWS, DMODEL, DMODEL);

    ln_kernel<<<NROWS, 256>>>(q_in, pP, gamma, beta, out);
}

// round 3
// speedup vs baseline: 1.2912x; 1.2912x over previous
#include <cuda_runtime.h>
#include <cuda_bf16.h>
#include <math.h>
#include <cstdint>

// Problem constants
#define BATCH   2
#define SLEN    2048
#define DMODEL  1024
#define NHEADS  16
#define HEADDIM 64
#define NROWS   (BATCH * SLEN)      // 4096
#define NGROUPS (BATCH * NHEADS)    // 32 reshaped "heads"

// Scratch (allocation-free rule: __device__ globals)
__device__ float g_Q[NROWS * DMODEL];
__device__ float g_K[NROWS * DMODEL];
__device__ float g_V[NROWS * DMODEL];
__device__ float g_O[NROWS * DMODEL];
__device__ float g_P[NROWS * DMODEL];
__device__ float g_WqT[DMODEL * DMODEL];
__device__ float g_WkT[DMODEL * DMODEL];
__device__ float g_WvT[DMODEL * DMODEL];
__device__ float g_WoT[DMODEL * DMODEL];

// ---------------------------------------------------------------------------
// Helpers (sm_80+ features only: mma.sync, cp.async, cvt.tf32 — NO tcgen05,
// the harness compiles at compute_103 which rejects all 'a'-gated PTX)
// ---------------------------------------------------------------------------
__device__ __forceinline__ uint32_t smem_u32(const void* p) {
    uint32_t a;
    asm("{ .reg .u64 t; cvta.to.shared.u64 t, %1; cvt.u32.u64 %0, t; }"
        : "=r"(a) : "l"(p));
    return a;
}

__device__ __forceinline__ uint32_t f2tf32(float f) {
    uint32_t r;
    asm("cvt.rna.tf32.f32 %0, %1;" : "=r"(r) : "f"(f));
    return r;
}

__device__ __forceinline__ void cp_async16(uint32_t saddr, const void* gaddr) {
    asm volatile("cp.async.cg.shared.global [%0], [%1], 16;"
                 :: "r"(saddr), "l"(gaddr) : "memory");
}
#define CP_COMMIT() asm volatile("cp.async.commit_group;" ::: "memory")
#define CP_WAIT1()  asm volatile("cp.async.wait_group 1;" ::: "memory")

__device__ __forceinline__ void mma_tf32(float* d, const uint32_t* a, const uint32_t* b) {
    asm volatile(
        "mma.sync.aligned.m16n8k8.row.col.f32.tf32.tf32.f32 "
        "{%0,%1,%2,%3}, {%4,%5,%6,%7}, {%8,%9}, {%0,%1,%2,%3};"
        : "+f"(d[0]), "+f"(d[1]), "+f"(d[2]), "+f"(d[3])
        : "r"(a[0]), "r"(a[1]), "r"(a[2]), "r"(a[3]), "r"(b[0]), "r"(b[1]));
}

// ---------------------------------------------------------------------------
// Weight transpose: Wt[n][k] = W[k][n], 1024x1024
// ---------------------------------------------------------------------------
__global__ __launch_bounds__(256) void transpose1024(
    const float* __restrict__ W, float* __restrict__ Wt)
{
    __shared__ float t[32][33];
    const int bx = blockIdx.x * 32, by = blockIdx.y * 32;
    const int x = threadIdx.x, y = threadIdx.y;   // 32 x 8
#pragma unroll
    for (int i = 0; i < 32; i += 8)
        t[y + i][x] = W[(size_t)(by + y + i) * DMODEL + bx + x];
    __syncthreads();
#pragma unroll
    for (int i = 0; i < 32; i += 8)
        Wt[(size_t)(bx + y + i) * DMODEL + by + x] = t[x][y + i];
}

// ---------------------------------------------------------------------------
// HMMA tf32 GEMM: C[M,N] = A[M,K] @ Bt[N,K]^T (+bias).
// A row-major (K contiguous), Bt row-major (K contiguous). K % 32 == 0.
// CTA 128x128, BK=32, 8 warps (4x2), warp tile 32x64 (2x8 m16n8k8 tiles).
// Smem: per buffer, A and B tiles stored [128 rows][36 floats] (stride 36 =>
// fragment loads hit banks (4*row+k)%32, all distinct => conflict-free).
// cp.async double-buffered pipeline.
// ---------------------------------------------------------------------------
#define RS 36   // smem row stride in floats
#define TILE_FLOATS (128 * RS)

__global__ __launch_bounds__(256) void gemm_mma_tf32(
    const float* __restrict__ A, const float* __restrict__ Bt,
    const float* __restrict__ bias, float* __restrict__ C,
    int M, int N, int K)
{
    extern __shared__ float sh[];
    float* sA[2] = { sh,                  sh + 2 * TILE_FLOATS };
    float* sB[2] = { sh + TILE_FLOATS,    sh + 3 * TILE_FLOATS };

    const int tid = threadIdx.x;
    const int wid = tid >> 5;
    const int lane = tid & 31;
    const int wm = wid & 3;          // 0..3 -> m offset
    const int wn = wid >> 2;         // 0..1 -> n offset
    const int mb = wm * 32;
    const int nb = wn * 64;
    const int g = lane >> 2;         // 0..7
    const int t = lane & 3;          // 0..3
    const int m0 = blockIdx.y * 128;
    const int n0 = blockIdx.x * 128;

    float acc[2][8][4];
#pragma unroll
    for (int i = 0; i < 2; i++)
#pragma unroll
        for (int j = 0; j < 8; j++)
#pragma unroll
            for (int q = 0; q < 4; q++) acc[i][j][q] = 0.f;

    const int NCH = K / 32;

    // issue loads of chunk c into buffer b (4 cp.async x2 per thread)
    auto issue = [&](int c, int b) {
        const float* Ag = A + (size_t)m0 * K + (size_t)c * 32;
        const float* Bg = Bt + (size_t)n0 * K + (size_t)c * 32;
        const uint32_t sa = smem_u32(sA[b]);
        const uint32_t sb = smem_u32(sB[b]);
#pragma unroll
        for (int i = 0; i < 4; i++) {
            const int u = tid + 256 * i;       // 0..1023
            const int row = u >> 3;
            const int seg = u & 7;
            const uint32_t so = (uint32_t)(row * RS + seg * 4) * 4u;
            cp_async16(sa + so, Ag + (size_t)row * K + seg * 4);
            cp_async16(sb + so, Bg + (size_t)row * K + seg * 4);
        }
        CP_COMMIT();
    };

    issue(0, 0);
    issue(1, 1);

    for (int c = 0; c < NCH; c++) {
        const int b = c & 1;
        CP_WAIT1();
        __syncthreads();

        const float* As_ = sA[b];
        const float* Bs_ = sB[b];
#pragma unroll
        for (int s = 0; s < 4; s++) {
            const int k0 = s * 8;
            uint32_t af[2][4];
#pragma unroll
            for (int mt = 0; mt < 2; mt++) {
                const int r0 = mb + mt * 16 + g;
                af[mt][0] = f2tf32(As_[r0 * RS + k0 + t]);
                af[mt][1] = f2tf32(As_[(r0 + 8) * RS + k0 + t]);
                af[mt][2] = f2tf32(As_[r0 * RS + k0 + t + 4]);
                af[mt][3] = f2tf32(As_[(r0 + 8) * RS + k0 + t + 4]);
            }
#pragma unroll
            for (int nt = 0; nt < 8; nt++) {
                const int nr = nb + nt * 8 + g;
                uint32_t bf[2];
                bf[0] = f2tf32(Bs_[nr * RS + k0 + t]);
                bf[1] = f2tf32(Bs_[nr * RS + k0 + t + 4]);
                mma_tf32(acc[0][nt], af[0], bf);
                mma_tf32(acc[1][nt], af[1], bf);
            }
        }
        __syncthreads();   // all warps done reading buf b before refill
        if (c + 2 < NCH) issue(c + 2, b);
        else CP_COMMIT();  // empty group keeps wait_group accounting uniform
    }

    // Epilogue: c0=[g][2t], c1=[g][2t+1], c2=[g+8][2t], c3=[g+8][2t+1]
#pragma unroll
    for (int mt = 0; mt < 2; mt++) {
        const int r = m0 + mb + mt * 16 + g;
#pragma unroll
        for (int nt = 0; nt < 8; nt++) {
            const int cx = n0 + nb + nt * 8 + 2 * t;
            float2 v0, v1;
            v0.x = acc[mt][nt][0]; v0.y = acc[mt][nt][1];
            v1.x = acc[mt][nt][2]; v1.y = acc[mt][nt][3];
            if (bias) {
                const float b0 = __ldg(&bias[cx]);
                const float b1 = __ldg(&bias[cx + 1]);
                v0.x += b0; v0.y += b1;
                v1.x += b0; v1.y += b1;
            }
            *(float2*)(C + (size_t)r * N + cx) = v0;
            *(float2*)(C + (size_t)(r + 8) * N + cx) = v1;
        }
    }
}

// ---------------------------------------------------------------------------
// Flash attention (unchanged from R1-passing): Q,K,V viewed as [32][2048][64].
// ---------------------------------------------------------------------------
__global__ __launch_bounds__(256) void attn_f32(
    const float* __restrict__ Q, const float* __restrict__ K,
    const float* __restrict__ V, const unsigned char* __restrict__ mask,
    float* __restrict__ O)
{
    extern __shared__ float sm[];
    float* sQ  = sm;
    float* sKT = sQ + 64 * 64;
    float* sPT = sKT + 64 * 68;
    float* sV  = sPT + 64 * 65;

    const int tid = threadIdx.x;
    const int tx = tid & 15;
    const int ty = tid >> 4;
    const int qb = blockIdx.x;
    const int g  = blockIdx.y;

    const float* Qh = Q + ((size_t)g * SLEN + qb * 64) * HEADDIM;
    const float* Kh = K + (size_t)g * SLEN * HEADDIM;
    const float* Vh = V + (size_t)g * SLEN * HEADDIM;
    const unsigned char* mrow =
        mask + (size_t)(g & (BATCH - 1)) * SLEN * SLEN + (size_t)(qb * 64) * SLEN;

    {
        const int r = tid >> 2;
        const int c = (tid & 3) * 16;
#pragma unroll
        for (int u = 0; u < 4; u++) {
            float4 v = *(const float4*)(Qh + r * 64 + c + u * 4);
            *(float4*)&sQ[r * 64 + c + u * 4] = v;
        }
    }

    float mrun[4], lrun[4];
    float o[4][4];
#pragma unroll
    for (int i = 0; i < 4; i++) {
        mrun[i] = -INFINITY;
        lrun[i] = 0.f;
#pragma unroll
        for (int j = 0; j < 4; j++) o[i][j] = 0.f;
    }

    const float scale = 0.125f;

    for (int kt = 0; kt < SLEN / 64; kt++) {
        __syncthreads();
        {
            const int r = tid >> 2;
            const int c = (tid & 3) * 16;
#pragma unroll
            for (int u = 0; u < 4; u++) {
                float4 kv = *(const float4*)(Kh + (size_t)(kt * 64 + r) * 64 + c + u * 4);
                sKT[(c + u * 4 + 0) * 68 + r] = kv.x;
                sKT[(c + u * 4 + 1) * 68 + r] = kv.y;
                sKT[(c + u * 4 + 2) * 68 + r] = kv.z;
                sKT[(c + u * 4 + 3) * 68 + r] = kv.w;
                float4 vv = *(const float4*)(Vh + (size_t)(kt * 64 + r) * 64 + c + u * 4);
                *(float4*)&sV[r * 64 + c + u * 4] = vv;
            }
        }
        __syncthreads();

        float sacc[4][4];
#pragma unroll
        for (int i = 0; i < 4; i++)
#pragma unroll
            for (int j = 0; j < 4; j++) sacc[i][j] = 0.f;

#pragma unroll 16
        for (int d = 0; d < 64; d++) {
            float4 bv = *(const float4*)&sKT[d * 68 + tx * 4];
            float a0 = sQ[(ty * 4 + 0) * 64 + d];
            float a1 = sQ[(ty * 4 + 1) * 64 + d];
            float a2 = sQ[(ty * 4 + 2) * 64 + d];
            float a3 = sQ[(ty * 4 + 3) * 64 + d];
            sacc[0][0] += a0 * bv.x; sacc[0][1] += a0 * bv.y; sacc[0][2] += a0 * bv.z; sacc[0][3] += a0 * bv.w;
            sacc[1][0] += a1 * bv.x; sacc[1][1] += a1 * bv.y; sacc[1][2] += a1 * bv.z; sacc[1][3] += a1 * bv.w;
            sacc[2][0] += a2 * bv.x; sacc[2][1] += a2 * bv.y; sacc[2][2] += a2 * bv.z; sacc[2][3] += a2 * bv.w;
            sacc[3][0] += a3 * bv.x; sacc[3][1] += a3 * bv.y; sacc[3][2] += a3 * bv.z; sacc[3][3] += a3 * bv.w;
        }

#pragma unroll
        for (int i = 0; i < 4; i++) {
            uchar4 mk = *(const uchar4*)(mrow + (size_t)(ty * 4 + i) * SLEN + kt * 64 + tx * 4);
            float s0 = mk.x ? -1e9f : sacc[i][0] * scale;
            float s1 = mk.y ? -1e9f : sacc[i][1] * scale;
            float s2 = mk.z ? -1e9f : sacc[i][2] * scale;
            float s3 = mk.w ? -1e9f : sacc[i][3] * scale;

            float rmax = fmaxf(fmaxf(s0, s1), fmaxf(s2, s3));
#pragma unroll
            for (int off = 8; off >= 1; off >>= 1)
                rmax = fmaxf(rmax, __shfl_xor_sync(0xffffffffu, rmax, off));

            float mnew = fmaxf(mrun[i], rmax);
            float p0 = __expf(s0 - mnew);
            float p1 = __expf(s1 - mnew);
            float p2 = __expf(s2 - mnew);
            float p3 = __expf(s3 - mnew);
            float rsum = p0 + p1 + p2 + p3;
#pragma unroll
            for (int off = 8; off >= 1; off >>= 1)
                rsum += __shfl_xor_sync(0xffffffffu, rsum, off);

            float corr = __expf(mrun[i] - mnew);
            lrun[i] = lrun[i] * corr + rsum;
            mrun[i] = mnew;
            o[i][0] *= corr; o[i][1] *= corr; o[i][2] *= corr; o[i][3] *= corr;

            const int r = ty * 4 + i;
            sPT[(tx * 4 + 0) * 65 + r] = p0;
            sPT[(tx * 4 + 1) * 65 + r] = p1;
            sPT[(tx * 4 + 2) * 65 + r] = p2;
            sPT[(tx * 4 + 3) * 65 + r] = p3;
        }
        __syncthreads();

#pragma unroll 16
        for (int k = 0; k < 64; k++) {
            float4 bv = *(const float4*)&sV[k * 64 + tx * 4];
            float a0 = sPT[k * 65 + ty * 4 + 0];
            float a1 = sPT[k * 65 + ty * 4 + 1];
            float a2 = sPT[k * 65 + ty * 4 + 2];
            float a3 = sPT[k * 65 + ty * 4 + 3];
            o[0][0] += a0 * bv.x; o[0][1] += a0 * bv.y; o[0][2] += a0 * bv.z; o[0][3] += a0 * bv.w;
            o[1][0] += a1 * bv.x; o[1][1] += a1 * bv.y; o[1][2] += a1 * bv.z; o[1][3] += a1 * bv.w;
            o[2][0] += a2 * bv.x; o[2][1] += a2 * bv.y; o[2][2] += a2 * bv.z; o[2][3] += a2 * bv.w;
            o[3][0] += a3 * bv.x; o[3][1] += a3 * bv.y; o[3][2] += a3 * bv.z; o[3][3] += a3 * bv.w;
        }
    }

#pragma unroll
    for (int i = 0; i < 4; i++) {
        float inv = 1.f / lrun[i];
        float4 v;
        v.x = o[i][0] * inv; v.y = o[i][1] * inv;
        v.z = o[i][2] * inv; v.w = o[i][3] * inv;
        size_t idx = ((size_t)g * SLEN + qb * 64 + ty * 4 + i) * HEADDIM + tx * 4;
        *(float4*)(O + idx) = v;
    }
}

// ---------------------------------------------------------------------------
// Fused residual + LayerNorm (unchanged from R1)
// ---------------------------------------------------------------------------
__global__ __launch_bounds__(256) void ln_kernel(
    const float* __restrict__ x, const float* __restrict__ p,
    const float* __restrict__ gamma, const float* __restrict__ beta,
    float* __restrict__ out)
{
    const int row = blockIdx.x;
    const int t = threadIdx.x;
    const size_t base = (size_t)row * DMODEL + t * 4;

    float4 xv = *(const float4*)(x + base);
    float4 pv = *(const float4*)(p + base);
    float v0 = xv.x + pv.x, v1 = xv.y + pv.y, v2 = xv.z + pv.z, v3 = xv.w + pv.w;

    __shared__ float red[8];
    float s = v0 + v1 + v2 + v3;
#pragma unroll
    for (int off = 16; off >= 1; off >>= 1) s += __shfl_xor_sync(0xffffffffu, s, off);
    if ((t & 31) == 0) red[t >> 5] = s;
    __syncthreads();
    float mu = (red[0] + red[1] + red[2] + red[3] +
                red[4] + red[5] + red[6] + red[7]) * (1.f / DMODEL);
    __syncthreads();

    float d0 = v0 - mu, d1 = v1 - mu, d2 = v2 - mu, d3 = v3 - mu;
    float q = d0 * d0 + d1 * d1 + d2 * d2 + d3 * d3;
#pragma unroll
    for (int off = 16; off >= 1; off >>= 1) q += __shfl_xor_sync(0xffffffffu, q, off);
    if ((t & 31) == 0) red[t >> 5] = q;
    __syncthreads();
    float var = (red[0] + red[1] + red[2] + red[3] +
                 red[4] + red[5] + red[6] + red[7]) * (1.f / DMODEL);
    float rs = rsqrtf(var + 1e-5f);

    float4 gv = *(const float4*)(gamma + t * 4);
    float4 bv = *(const float4*)(beta + t * 4);
    float4 ov;
    ov.x = d0 * rs * gv.x + bv.x;
    ov.y = d1 * rs * gv.y + bv.y;
    ov.z = d2 * rs * gv.z + bv.z;
    ov.w = d3 * rs * gv.w + bv.w;
    *(float4*)(out + base) = ov;
}

// ---------------------------------------------------------------------------
// Launch
// ---------------------------------------------------------------------------
extern "C" void kernel_launch(void* const* d_in, const int* in_sizes, int n_in,
                              void* d_out, int out_size)
{
    (void)in_sizes; (void)n_in; (void)out_size;
    const float* q_in  = (const float*)d_in[0];
    const float* k_in  = (const float*)d_in[1];
    const float* v_in  = (const float*)d_in[2];
    const unsigned char* mask = (const unsigned char*)d_in[3];
    const float* Wq = (const float*)d_in[4];
    const float* Wk = (const float*)d_in[5];
    const float* Wv = (const float*)d_in[6];
    const float* Wo = (const float*)d_in[7];
    const float* bo = (const float*)d_in[8];
    const float* gamma = (const float*)d_in[9];
    const float* beta  = (const float*)d_in[10];
    float* out = (float*)d_out;

    float *pQ, *pK, *pV, *pO, *pP, *pWqT, *pWkT, *pWvT, *pWoT;
    cudaGetSymbolAddress((void**)&pQ, g_Q);
    cudaGetSymbolAddress((void**)&pK, g_K);
    cudaGetSymbolAddress((void**)&pV, g_V);
    cudaGetSymbolAddress((void**)&pO, g_O);
    cudaGetSymbolAddress((void**)&pP, g_P);
    cudaGetSymbolAddress((void**)&pWqT, g_WqT);
    cudaGetSymbolAddress((void**)&pWkT, g_WkT);
    cudaGetSymbolAddress((void**)&pWvT, g_WvT);
    cudaGetSymbolAddress((void**)&pWoT, g_WoT);

    const int attn_smem = (64 * 64 + 64 * 68 + 64 * 65 + 64 * 64) * (int)sizeof(float);
    cudaFuncSetAttribute(attn_f32, cudaFuncAttributeMaxDynamicSharedMemorySize, attn_smem);
    const int gemm_smem = 4 * TILE_FLOATS * (int)sizeof(float);   // 73728 B
    cudaFuncSetAttribute(gemm_mma_tf32, cudaFuncAttributeMaxDynamicSharedMemorySize, gemm_smem);

    // transpose weights to [N, K] (K-major B operand)
    dim3 tgrid(DMODEL / 32, DMODEL / 32);
    dim3 tblk(32, 8);
    transpose1024<<<tgrid, tblk>>>(Wq, pWqT);
    transpose1024<<<tgrid, tblk>>>(Wk, pWkT);
    transpose1024<<<tgrid, tblk>>>(Wv, pWvT);
    transpose1024<<<tgrid, tblk>>>(Wo, pWoT);

    dim3 ggrid(DMODEL / 128, NROWS / 128);    // (8, 32)
    gemm_mma_tf32<<<ggrid, 256, gemm_smem>>>(q_in, pWqT, nullptr, pQ, NROWS, DMODEL, DMODEL);
    gemm_mma_tf32<<<ggrid, 256, gemm_smem>>>(k_in, pWkT, nullptr, pK, NROWS, DMODEL, DMODEL);
    gemm_mma_tf32<<<ggrid, 256, gemm_smem>>>(v_in, pWvT, nullptr, pV, NROWS, DMODEL, DMODEL);

    dim3 agrid(SLEN / 64, NGROUPS);           // (32, 32)
    attn_f32<<<agrid, 256, attn_smem>>>(pQ, pK, pV, mask, pO);

    gemm_mma_tf32<<<ggrid, 256, gemm_smem>>>(pO, pWoT, bo, pP, NROWS, DMODEL, DMODEL);

    ln_kernel<<<NROWS, 256>>>(q_in, pP, gamma, beta, out);
}

// round 5
// speedup vs baseline: 2.4104x; 1.8668x over previous
#include <cuda_runtime.h>
#include <cuda_bf16.h>
#include <math.h>
#include <cstdint>

// Problem constants
#define BATCH   2
#define SLEN    2048
#define DMODEL  1024
#define NHEADS  16
#define HEADDIM 64
#define NROWS   (BATCH * SLEN)      // 4096
#define NGROUPS (BATCH * NHEADS)    // 32 reshaped "heads"

// Scratch (allocation-free rule: __device__ globals)
__device__ float g_Q[NROWS * DMODEL];
__device__ float g_K[NROWS * DMODEL];
__device__ float g_V[NROWS * DMODEL];
__device__ float g_VT[NROWS * DMODEL];   // per-group transposed V: [32][64][2048]
__device__ float g_O[NROWS * DMODEL];
__device__ float g_P[NROWS * DMODEL];
__device__ float g_WqT[DMODEL * DMODEL];
__device__ float g_WkT[DMODEL * DMODEL];
__device__ float g_WvT[DMODEL * DMODEL];
__device__ float g_WoT[DMODEL * DMODEL];

// ---------------------------------------------------------------------------
// Helpers (sm_80+ only: mma.sync, cp.async, cvt.tf32 — compute_103 rejects
// all 'a'-gated PTX like tcgen05, so HMMA is the tensor path here)
// ---------------------------------------------------------------------------
__device__ __forceinline__ uint32_t smem_u32(const void* p) {
    uint32_t a;
    asm("{ .reg .u64 t; cvta.to.shared.u64 t, %1; cvt.u32.u64 %0, t; }"
        : "=r"(a) : "l"(p));
    return a;
}

__device__ __forceinline__ uint32_t f2tf32(float f) {
    uint32_t r;
    asm("cvt.rna.tf32.f32 %0, %1;" : "=r"(r) : "f"(f));
    return r;
}

__device__ __forceinline__ void cp_async16(uint32_t saddr, const void* gaddr) {
    asm volatile("cp.async.cg.shared.global [%0], [%1], 16;"
                 :: "r"(saddr), "l"(gaddr) : "memory");
}
#define CP_COMMIT() asm volatile("cp.async.commit_group;" ::: "memory")
#define CP_WAIT1()  asm volatile("cp.async.wait_group 1;" ::: "memory")

__device__ __forceinline__ void mma_tf32(float* d, const uint32_t* a, const uint32_t* b) {
    asm volatile(
        "mma.sync.aligned.m16n8k8.row.col.f32.tf32.tf32.f32 "
        "{%0,%1,%2,%3}, {%4,%5,%6,%7}, {%8,%9}, {%0,%1,%2,%3};"
        : "+f"(d[0]), "+f"(d[1]), "+f"(d[2]), "+f"(d[3])
        : "r"(a[0]), "r"(a[1]), "r"(a[2]), "r"(a[3]), "r"(b[0]), "r"(b[1]));
}

// ---------------------------------------------------------------------------
// Weight transpose: Wt[n][k] = W[k][n], 1024x1024
// ---------------------------------------------------------------------------
__global__ __launch_bounds__(256) void transpose1024(
    const float* __restrict__ W, float* __restrict__ Wt)
{
    __shared__ float t[32][33];
    const int bx = blockIdx.x * 32, by = blockIdx.y * 32;
    const int x = threadIdx.x, y = threadIdx.y;   // 32 x 8
#pragma unroll
    for (int i = 0; i < 32; i += 8)
        t[y + i][x] = W[(size_t)(by + y + i) * DMODEL + bx + x];
    __syncthreads();
#pragma unroll
    for (int i = 0; i < 32; i += 8)
        Wt[(size_t)(bx + y + i) * DMODEL + by + x] = t[x][y + i];
}

// ---------------------------------------------------------------------------
// V transpose per group: V[g][s][d] (g in 0..31, s 2048, d 64) -> VT[g][d][s]
// ---------------------------------------------------------------------------
__global__ __launch_bounds__(256) void vtranspose(
    const float* __restrict__ V, float* __restrict__ VT)
{
    __shared__ float t[32][33];
    const int g = blockIdx.z;
    const int s0 = blockIdx.x * 32, d0 = blockIdx.y * 32;
    const int x = threadIdx.x, y = threadIdx.y;   // 32 x 8
    const float* Vg = V + (size_t)g * SLEN * HEADDIM;
    float* VTg = VT + (size_t)g * SLEN * HEADDIM;
#pragma unroll
    for (int i = 0; i < 32; i += 8)
        t[y + i][x] = Vg[(size_t)(s0 + y + i) * HEADDIM + d0 + x];
    __syncthreads();
#pragma unroll
    for (int i = 0; i < 32; i += 8)
        VTg[(size_t)(d0 + y + i) * SLEN + s0 + x] = t[x][y + i];
}

// ---------------------------------------------------------------------------
// HMMA tf32 GEMM (unchanged from R3-passing): C = A @ Bt^T (+bias)
// ---------------------------------------------------------------------------
#define RS 36
#define TILE_FLOATS (128 * RS)

__global__ __launch_bounds__(256) void gemm_mma_tf32(
    const float* __restrict__ A, const float* __restrict__ Bt,
    const float* __restrict__ bias, float* __restrict__ C,
    int M, int N, int K)
{
    extern __shared__ float sh[];
    float* sA[2] = { sh,                  sh + 2 * TILE_FLOATS };
    float* sB[2] = { sh + TILE_FLOATS,    sh + 3 * TILE_FLOATS };

    const int tid = threadIdx.x;
    const int wid = tid >> 5;
    const int lane = tid & 31;
    const int wm = wid & 3;
    const int wn = wid >> 2;
    const int mb = wm * 32;
    const int nb = wn * 64;
    const int g = lane >> 2;
    const int t = lane & 3;
    const int m0 = blockIdx.y * 128;
    const int n0 = blockIdx.x * 128;

    float acc[2][8][4];
#pragma unroll
    for (int i = 0; i < 2; i++)
#pragma unroll
        for (int j = 0; j < 8; j++)
#pragma unroll
            for (int q = 0; q < 4; q++) acc[i][j][q] = 0.f;

    const int NCH = K / 32;

    auto issue = [&](int c, int b) {
        const float* Ag = A + (size_t)m0 * K + (size_t)c * 32;
        const float* Bg = Bt + (size_t)n0 * K + (size_t)c * 32;
        const uint32_t sa = smem_u32(sA[b]);
        const uint32_t sb = smem_u32(sB[b]);
#pragma unroll
        for (int i = 0; i < 4; i++) {
            const int u = tid + 256 * i;
            const int row = u >> 3;
            const int seg = u & 7;
            const uint32_t so = (uint32_t)(row * RS + seg * 4) * 4u;
            cp_async16(sa + so, Ag + (size_t)row * K + seg * 4);
            cp_async16(sb + so, Bg + (size_t)row * K + seg * 4);
        }
        CP_COMMIT();
    };

    issue(0, 0);
    issue(1, 1);

    for (int c = 0; c < NCH; c++) {
        const int b = c & 1;
        CP_WAIT1();
        __syncthreads();

        const float* As_ = sA[b];
        const float* Bs_ = sB[b];
#pragma unroll
        for (int s = 0; s < 4; s++) {
            const int k0 = s * 8;
            uint32_t af[2][4];
#pragma unroll
            for (int mt = 0; mt < 2; mt++) {
                const int r0 = mb + mt * 16 + g;
                af[mt][0] = f2tf32(As_[r0 * RS + k0 + t]);
                af[mt][1] = f2tf32(As_[(r0 + 8) * RS + k0 + t]);
                af[mt][2] = f2tf32(As_[r0 * RS + k0 + t + 4]);
                af[mt][3] = f2tf32(As_[(r0 + 8) * RS + k0 + t + 4]);
            }
#pragma unroll
            for (int nt = 0; nt < 8; nt++) {
                const int nr = nb + nt * 8 + g;
                uint32_t bf[2];
                bf[0] = f2tf32(Bs_[nr * RS + k0 + t]);
                bf[1] = f2tf32(Bs_[nr * RS + k0 + t + 4]);
                mma_tf32(acc[0][nt], af[0], bf);
                mma_tf32(acc[1][nt], af[1], bf);
            }
        }
        __syncthreads();
        if (c + 2 < NCH) issue(c + 2, b);
        else CP_COMMIT();
    }

#pragma unroll
    for (int mt = 0; mt < 2; mt++) {
        const int r = m0 + mb + mt * 16 + g;
#pragma unroll
        for (int nt = 0; nt < 8; nt++) {
            const int cx = n0 + nb + nt * 8 + 2 * t;
            float2 v0, v1;
            v0.x = acc[mt][nt][0]; v0.y = acc[mt][nt][1];
            v1.x = acc[mt][nt][2]; v1.y = acc[mt][nt][3];
            if (bias) {
                const float b0 = __ldg(&bias[cx]);
                const float b1 = __ldg(&bias[cx + 1]);
                v0.x += b0; v0.y += b1;
                v1.x += b0; v1.y += b1;
            }
            *(float2*)(C + (size_t)r * N + cx) = v0;
            *(float2*)(C + (size_t)(r + 8) * N + cx) = v1;
        }
    }
}

// ---------------------------------------------------------------------------
// HMMA tf32 flash attention. Q,K viewed [32][2048][64]; VT is [32][64][2048].
// CTA: 128 Q rows x 1 group, *** 8 warps (16 rows each) *** — R4's bug was
// 4 warps covering only 64 of the 128 rows (half of O silently zero).
// smem (tf32 bits): sK[64][68], sVT[64][68], sP[128][68] = 69632 B.
// Stride 68 => fragment loads hit bank (4*g + t + const) % 32: conflict-free.
// ---------------------------------------------------------------------------
#define ATS 68   // attention smem row stride (words)

__global__ __launch_bounds__(256) void attn_mma(
    const float* __restrict__ Q, const float* __restrict__ K,
    const float* __restrict__ VT, const unsigned char* __restrict__ mask,
    float* __restrict__ O)
{
    extern __shared__ uint32_t smw[];
    uint32_t* sK  = smw;                 // [64][ATS]
    uint32_t* sVT = smw + 64 * ATS;      // [64][ATS]
    uint32_t* sP  = smw + 2 * 64 * ATS;  // [128][ATS]

    const int tid = threadIdx.x;
    const int wid = tid >> 5;            // 0..7
    const int lane = tid & 31;
    const int gq = lane >> 2;            // 0..7
    const int t = lane & 3;              // 0..3
    const int qb = blockIdx.x;           // 0..15
    const int grp = blockIdx.y;          // 0..31
    const int r0 = wid * 16;             // warp's row base: 0..112 (covers 128)

    const float* Qg = Q + ((size_t)grp * SLEN + qb * 128 + r0) * HEADDIM;
    const float* Kg = K + (size_t)grp * SLEN * HEADDIM;
    const float* VTg = VT + (size_t)grp * SLEN * HEADDIM;
    const unsigned char* mrow =
        mask + (size_t)(grp % BATCH) * SLEN * SLEN + (size_t)(qb * 128 + r0) * SLEN;

    // ---- Stage Q (warp-private rows of sP), build persistent A fragments
    uint32_t* sQw = sP + r0 * ATS;
    {
        const int row = lane >> 1;           // 0..15
        const int cs = (lane & 1) * 32;      // 0 or 32
#pragma unroll
        for (int j = 0; j < 8; j++) {
            float4 v = *(const float4*)(Qg + row * HEADDIM + cs + j * 4);
            uint4 u;
            u.x = f2tf32(v.x); u.y = f2tf32(v.y);
            u.z = f2tf32(v.z); u.w = f2tf32(v.w);
            *(uint4*)&sQw[row * ATS + cs + j * 4] = u;
        }
    }
    __syncwarp();
    uint32_t qf[8][4];
#pragma unroll
    for (int ks = 0; ks < 8; ks++) {
        const int k0 = ks * 8;
        qf[ks][0] = sQw[gq * ATS + k0 + t];
        qf[ks][1] = sQw[(gq + 8) * ATS + k0 + t];
        qf[ks][2] = sQw[gq * ATS + k0 + t + 4];
        qf[ks][3] = sQw[(gq + 8) * ATS + k0 + t + 4];
    }
    __syncwarp();

    float oacc[8][4];
#pragma unroll
    for (int nt = 0; nt < 8; nt++)
#pragma unroll
        for (int q = 0; q < 4; q++) oacc[nt][q] = 0.f;
    float mA = -INFINITY, mB = -INFINITY, lA = 0.f, lB = 0.f;

    const float scale = 0.125f;   // 1/sqrt(64)
    uint32_t* sPw = sP + r0 * ATS;

    for (int kt = 0; kt < SLEN / 64; kt++) {
        __syncthreads();   // prior tile's sK/sVT reads complete
        // ---- Load K tile [64 keys][64 dims], VT tile [64 dims][64 keys]
        // 256 threads: row = tid/4, 16-float slice per thread.
        {
            const int row = tid >> 2;        // 0..63
            const int cs = (tid & 3) * 16;   // 0,16,32,48
            const float* Kp = Kg + (size_t)(kt * 64 + row) * HEADDIM + cs;
            const float* Vp = VTg + (size_t)row * SLEN + kt * 64 + cs;
#pragma unroll
            for (int j = 0; j < 4; j++) {
                float4 kv = *(const float4*)(Kp + j * 4);
                uint4 ku;
                ku.x = f2tf32(kv.x); ku.y = f2tf32(kv.y);
                ku.z = f2tf32(kv.z); ku.w = f2tf32(kv.w);
                *(uint4*)&sK[row * ATS + cs + j * 4] = ku;
                float4 vv = *(const float4*)(Vp + j * 4);
                uint4 vu;
                vu.x = f2tf32(vv.x); vu.y = f2tf32(vv.y);
                vu.z = f2tf32(vv.z); vu.w = f2tf32(vv.w);
                *(uint4*)&sVT[row * ATS + cs + j * 4] = vu;
            }
        }
        __syncthreads();

        // ---- S = Q K^T  (m16 x n64, K=64)
        float sacc[8][4];
#pragma unroll
        for (int nt = 0; nt < 8; nt++)
#pragma unroll
            for (int q = 0; q < 4; q++) sacc[nt][q] = 0.f;
#pragma unroll
        for (int ks = 0; ks < 8; ks++) {
            const int k0 = ks * 8;
#pragma unroll
            for (int nt = 0; nt < 8; nt++) {
                uint32_t bf[2];
                bf[0] = sK[(nt * 8 + gq) * ATS + k0 + t];
                bf[1] = sK[(nt * 8 + gq) * ATS + k0 + t + 4];
                mma_tf32(sacc[nt], qf[ks], bf);
            }
        }

        // ---- Mask + scale (rows gq and gq+8; cols nt*8 + 2t, +1)
#pragma unroll
        for (int nt = 0; nt < 8; nt++) {
            const int cb = kt * 64 + nt * 8 + 2 * t;
            uchar2 ma = *(const uchar2*)(mrow + (size_t)gq * SLEN + cb);
            uchar2 mb2 = *(const uchar2*)(mrow + (size_t)(gq + 8) * SLEN + cb);
            sacc[nt][0] = ma.x ? -1e9f : sacc[nt][0] * scale;
            sacc[nt][1] = ma.y ? -1e9f : sacc[nt][1] * scale;
            sacc[nt][2] = mb2.x ? -1e9f : sacc[nt][2] * scale;
            sacc[nt][3] = mb2.y ? -1e9f : sacc[nt][3] * scale;
        }

        // ---- Online softmax (row reduction across the 4-lane t-group)
        float mxA = -INFINITY, mxB = -INFINITY;
#pragma unroll
        for (int nt = 0; nt < 8; nt++) {
            mxA = fmaxf(mxA, fmaxf(sacc[nt][0], sacc[nt][1]));
            mxB = fmaxf(mxB, fmaxf(sacc[nt][2], sacc[nt][3]));
        }
        mxA = fmaxf(mxA, __shfl_xor_sync(0xffffffffu, mxA, 1));
        mxA = fmaxf(mxA, __shfl_xor_sync(0xffffffffu, mxA, 2));
        mxB = fmaxf(mxB, __shfl_xor_sync(0xffffffffu, mxB, 1));
        mxB = fmaxf(mxB, __shfl_xor_sync(0xffffffffu, mxB, 2));

        const float mnA = fmaxf(mA, mxA);
        const float mnB = fmaxf(mB, mxB);
        const float cA = __expf(mA - mnA);
        const float cB = __expf(mB - mnB);
        float suA = 0.f, suB = 0.f;
#pragma unroll
        for (int nt = 0; nt < 8; nt++) {
            sacc[nt][0] = __expf(sacc[nt][0] - mnA);
            sacc[nt][1] = __expf(sacc[nt][1] - mnA);
            sacc[nt][2] = __expf(sacc[nt][2] - mnB);
            sacc[nt][3] = __expf(sacc[nt][3] - mnB);
            suA += sacc[nt][0] + sacc[nt][1];
            suB += sacc[nt][2] + sacc[nt][3];
        }
        suA += __shfl_xor_sync(0xffffffffu, suA, 1);
        suA += __shfl_xor_sync(0xffffffffu, suA, 2);
        suB += __shfl_xor_sync(0xffffffffu, suB, 1);
        suB += __shfl_xor_sync(0xffffffffu, suB, 2);
        lA = lA * cA + suA;
        lB = lB * cB + suB;
        mA = mnA;
        mB = mnB;
#pragma unroll
        for (int nt = 0; nt < 8; nt++) {
            oacc[nt][0] *= cA; oacc[nt][1] *= cA;
            oacc[nt][2] *= cB; oacc[nt][3] *= cB;
        }

        // ---- Stage P (tf32 bits) in warp-private smem rows
#pragma unroll
        for (int nt = 0; nt < 8; nt++) {
            const int cb = nt * 8 + 2 * t;
            sPw[gq * ATS + cb]       = f2tf32(sacc[nt][0]);
            sPw[gq * ATS + cb + 1]   = f2tf32(sacc[nt][1]);
            sPw[(gq + 8) * ATS + cb]     = f2tf32(sacc[nt][2]);
            sPw[(gq + 8) * ATS + cb + 1] = f2tf32(sacc[nt][3]);
        }
        __syncwarp();

        // ---- O += P V  (k = 64 keys, n = 64 dims)
#pragma unroll
        for (int ks = 0; ks < 8; ks++) {
            const int k0 = ks * 8;
            uint32_t af[4];
            af[0] = sPw[gq * ATS + k0 + t];
            af[1] = sPw[(gq + 8) * ATS + k0 + t];
            af[2] = sPw[gq * ATS + k0 + t + 4];
            af[3] = sPw[(gq + 8) * ATS + k0 + t + 4];
#pragma unroll
            for (int nt = 0; nt < 8; nt++) {
                uint32_t bf[2];
                bf[0] = sVT[(nt * 8 + gq) * ATS + k0 + t];
                bf[1] = sVT[(nt * 8 + gq) * ATS + k0 + t + 4];
                mma_tf32(oacc[nt], af, bf);
            }
        }
        __syncwarp();   // PV reads of sPw done before next tile overwrites
    }

    // ---- Normalize + write O (flat [32][2048][64])
    const float iA = 1.f / lA;
    const float iB = 1.f / lB;
    float* Og = O + ((size_t)grp * SLEN + qb * 128 + r0) * HEADDIM;
#pragma unroll
    for (int nt = 0; nt < 8; nt++) {
        const int cb = nt * 8 + 2 * t;
        float2 vA, vB;
        vA.x = oacc[nt][0] * iA; vA.y = oacc[nt][1] * iA;
        vB.x = oacc[nt][2] * iB; vB.y = oacc[nt][3] * iB;
        *(float2*)(Og + (size_t)gq * HEADDIM + cb) = vA;
        *(float2*)(Og + (size_t)(gq + 8) * HEADDIM + cb) = vB;
    }
}

// ---------------------------------------------------------------------------
// Fused residual + LayerNorm (unchanged)
// ---------------------------------------------------------------------------
__global__ __launch_bounds__(256) void ln_kernel(
    const float* __restrict__ x, const float* __restrict__ p,
    const float* __restrict__ gamma, const float* __restrict__ beta,
    float* __restrict__ out)
{
    const int row = blockIdx.x;
    const int t = threadIdx.x;
    const size_t base = (size_t)row * DMODEL + t * 4;

    float4 xv = *(const float4*)(x + base);
    float4 pv = *(const float4*)(p + base);
    float v0 = xv.x + pv.x, v1 = xv.y + pv.y, v2 = xv.z + pv.z, v3 = xv.w + pv.w;

    __shared__ float red[8];
    float s = v0 + v1 + v2 + v3;
#pragma unroll
    for (int off = 16; off >= 1; off >>= 1) s += __shfl_xor_sync(0xffffffffu, s, off);
    if ((t & 31) == 0) red[t >> 5] = s;
    __syncthreads();
    float mu = (red[0] + red[1] + red[2] + red[3] +
                red[4] + red[5] + red[6] + red[7]) * (1.f / DMODEL);
    __syncthreads();

    float d0 = v0 - mu, d1 = v1 - mu, d2 = v2 - mu, d3 = v3 - mu;
    float q = d0 * d0 + d1 * d1 + d2 * d2 + d3 * d3;
#pragma unroll
    for (int off = 16; off >= 1; off >>= 1) q += __shfl_xor_sync(0xffffffffu, q, off);
    if ((t & 31) == 0) red[t >> 5] = q;
    __syncthreads();
    float var = (red[0] + red[1] + red[2] + red[3] +
                 red[4] + red[5] + red[6] + red[7]) * (1.f / DMODEL);
    float rs = rsqrtf(var + 1e-5f);

    float4 gv = *(const float4*)(gamma + t * 4);
    float4 bv = *(const float4*)(beta + t * 4);
    float4 ov;
    ov.x = d0 * rs * gv.x + bv.x;
    ov.y = d1 * rs * gv.y + bv.y;
    ov.z = d2 * rs * gv.z + bv.z;
    ov.w = d3 * rs * gv.w + bv.w;
    *(float4*)(out + base) = ov;
}

// ---------------------------------------------------------------------------
// Launch
// ---------------------------------------------------------------------------
extern "C" void kernel_launch(void* const* d_in, const int* in_sizes, int n_in,
                              void* d_out, int out_size)
{
    (void)in_sizes; (void)n_in; (void)out_size;
    const float* q_in  = (const float*)d_in[0];
    const float* k_in  = (const float*)d_in[1];
    const float* v_in  = (const float*)d_in[2];
    const unsigned char* mask = (const unsigned char*)d_in[3];
    const float* Wq = (const float*)d_in[4];
    const float* Wk = (const float*)d_in[5];
    const float* Wv = (const float*)d_in[6];
    const float* Wo = (const float*)d_in[7];
    const float* bo = (const float*)d_in[8];
    const float* gamma = (const float*)d_in[9];
    const float* beta  = (const float*)d_in[10];
    float* out = (float*)d_out;

    float *pQ, *pK, *pV, *pVT, *pO, *pP, *pWqT, *pWkT, *pWvT, *pWoT;
    cudaGetSymbolAddress((void**)&pQ, g_Q);
    cudaGetSymbolAddress((void**)&pK, g_K);
    cudaGetSymbolAddress((void**)&pV, g_V);
    cudaGetSymbolAddress((void**)&pVT, g_VT);
    cudaGetSymbolAddress((void**)&pO, g_O);
    cudaGetSymbolAddress((void**)&pP, g_P);
    cudaGetSymbolAddress((void**)&pWqT, g_WqT);
    cudaGetSymbolAddress((void**)&pWkT, g_WkT);
    cudaGetSymbolAddress((void**)&pWvT, g_WvT);
    cudaGetSymbolAddress((void**)&pWoT, g_WoT);

    const int gemm_smem = 4 * TILE_FLOATS * (int)sizeof(float);   // 73728 B
    cudaFuncSetAttribute(gemm_mma_tf32, cudaFuncAttributeMaxDynamicSharedMemorySize, gemm_smem);
    const int attn_smem = (2 * 64 * ATS + 128 * ATS) * (int)sizeof(uint32_t);  // 69632 B
    cudaFuncSetAttribute(attn_mma, cudaFuncAttributeMaxDynamicSharedMemorySize, attn_smem);

    // transpose weights to [N, K]
    dim3 tgrid(DMODEL / 32, DMODEL / 32);
    dim3 tblk(32, 8);
    transpose1024<<<tgrid, tblk>>>(Wq, pWqT);
    transpose1024<<<tgrid, tblk>>>(Wk, pWkT);
    transpose1024<<<tgrid, tblk>>>(Wv, pWvT);
    transpose1024<<<tgrid, tblk>>>(Wo, pWoT);

    dim3 ggrid(DMODEL / 128, NROWS / 128);    // (8, 32)
    gemm_mma_tf32<<<ggrid, 256, gemm_smem>>>(q_in, pWqT, nullptr, pQ, NROWS, DMODEL, DMODEL);
    gemm_mma_tf32<<<ggrid, 256, gemm_smem>>>(k_in, pWkT, nullptr, pK, NROWS, DMODEL, DMODEL);
    gemm_mma_tf32<<<ggrid, 256, gemm_smem>>>(v_in, pWvT, nullptr, pV, NROWS, DMODEL, DMODEL);

    // V -> VT per group
    dim3 vgrid(SLEN / 32, HEADDIM / 32, NGROUPS);
    vtranspose<<<vgrid, tblk>>>(pV, pVT);

    dim3 agrid(SLEN / 128, NGROUPS);          // (16, 32), 8 warps/CTA -> 128 rows
    attn_mma<<<agrid, 256, attn_smem>>>(pQ, pK, pVT, mask, pO);

    gemm_mma_tf32<<<ggrid, 256, gemm_smem>>>(pO, pWoT, bo, pP, NROWS, DMODEL, DMODEL);

    ln_kernel<<<NROWS, 256>>>(q_in, pP, gamma, beta, out);
}

// round 6
// speedup vs baseline: 3.1523x; 1.3078x over previous
#include <cuda_runtime.h>
#include <cuda_bf16.h>
#include <math.h>
#include <cstdint>

// Problem constants
#define BATCH   2
#define SLEN    2048
#define DMODEL  1024
#define NHEADS  16
#define HEADDIM 64
#define NROWS   (BATCH * SLEN)      // 4096
#define NGROUPS (BATCH * NHEADS)    // 32 reshaped "heads"

// Scratch (allocation-free rule: __device__ globals)
__device__ float g_Q[NROWS * DMODEL];
__device__ float g_K[NROWS * DMODEL];
__device__ float g_V[NROWS * DMODEL];
__device__ float g_VT[NROWS * DMODEL];        // per-group transposed V
__device__ float g_P[NROWS * DMODEL];
__device__ __nv_bfloat16 g_Ob[NROWS * DMODEL];   // attention output (bf16)
__device__ __nv_bfloat16 g_Qin[NROWS * DMODEL];  // bf16 copies of inputs
__device__ __nv_bfloat16 g_Kin[NROWS * DMODEL];
__device__ __nv_bfloat16 g_Vin[NROWS * DMODEL];
__device__ __nv_bfloat16 g_WqT[DMODEL * DMODEL]; // bf16 transposed weights
__device__ __nv_bfloat16 g_WkT[DMODEL * DMODEL];
__device__ __nv_bfloat16 g_WvT[DMODEL * DMODEL];
__device__ __nv_bfloat16 g_WoT[DMODEL * DMODEL];

// ---------------------------------------------------------------------------
// Helpers (sm_80+ only — compute_103 rejects 'a'-gated PTX like tcgen05)
// ---------------------------------------------------------------------------
__device__ __forceinline__ uint32_t smem_u32(const void* p) {
    uint32_t a;
    asm("{ .reg .u64 t; cvta.to.shared.u64 t, %1; cvt.u32.u64 %0, t; }"
        : "=r"(a) : "l"(p));
    return a;
}

__device__ __forceinline__ uint32_t f2tf32(float f) {
    uint32_t r;
    asm("cvt.rna.tf32.f32 %0, %1;" : "=r"(r) : "f"(f));
    return r;
}

__device__ __forceinline__ void cp_async16(uint32_t saddr, const void* gaddr) {
    asm volatile("cp.async.cg.shared.global [%0], [%1], 16;"
                 :: "r"(saddr), "l"(gaddr) : "memory");
}
#define CP_COMMIT() asm volatile("cp.async.commit_group;" ::: "memory")
#define CP_WAIT1()  asm volatile("cp.async.wait_group 1;" ::: "memory")

__device__ __forceinline__ void mma_tf32(float* d, const uint32_t* a, const uint32_t* b) {
    asm volatile(
        "mma.sync.aligned.m16n8k8.row.col.f32.tf32.tf32.f32 "
        "{%0,%1,%2,%3}, {%4,%5,%6,%7}, {%8,%9}, {%0,%1,%2,%3};"
        : "+f"(d[0]), "+f"(d[1]), "+f"(d[2]), "+f"(d[3])
        : "r"(a[0]), "r"(a[1]), "r"(a[2]), "r"(a[3]), "r"(b[0]), "r"(b[1]));
}

__device__ __forceinline__ void mma_bf16(float* d, const uint32_t* a, const uint32_t* b) {
    asm volatile(
        "mma.sync.aligned.m16n8k16.row.col.f32.bf16.bf16.f32 "
        "{%0,%1,%2,%3}, {%4,%5,%6,%7}, {%8,%9}, {%0,%1,%2,%3};"
        : "+f"(d[0]), "+f"(d[1]), "+f"(d[2]), "+f"(d[3])
        : "r"(a[0]), "r"(a[1]), "r"(a[2]), "r"(a[3]), "r"(b[0]), "r"(b[1]));
}

// ---------------------------------------------------------------------------
// fp32 -> bf16 conversion (8 elements/thread)
// ---------------------------------------------------------------------------
__global__ __launch_bounds__(256) void cvt_bf16(
    const float* __restrict__ x, __nv_bfloat16* __restrict__ y)
{
    const size_t i = ((size_t)blockIdx.x * 256 + threadIdx.x) * 8;
    float4 a = *(const float4*)(x + i);
    float4 b = *(const float4*)(x + i + 4);
    __nv_bfloat162* yp = reinterpret_cast<__nv_bfloat162*>(y + i);
    yp[0] = __floats2bfloat162_rn(a.x, a.y);
    yp[1] = __floats2bfloat162_rn(a.z, a.w);
    yp[2] = __floats2bfloat162_rn(b.x, b.y);
    yp[3] = __floats2bfloat162_rn(b.z, b.w);
}

// ---------------------------------------------------------------------------
// Weight transpose (fp32 -> bf16): Wt[n][k] = bf16(W[k][n]), 1024x1024
// ---------------------------------------------------------------------------
__global__ __launch_bounds__(256) void transpose1024_bf16(
    const float* __restrict__ W, __nv_bfloat16* __restrict__ Wt)
{
    __shared__ float t[32][33];
    const int bx = blockIdx.x * 32, by = blockIdx.y * 32;
    const int x = threadIdx.x, y = threadIdx.y;   // 32 x 8
#pragma unroll
    for (int i = 0; i < 32; i += 8)
        t[y + i][x] = W[(size_t)(by + y + i) * DMODEL + bx + x];
    __syncthreads();
#pragma unroll
    for (int i = 0; i < 32; i += 8)
        Wt[(size_t)(bx + y + i) * DMODEL + by + x] = __float2bfloat16_rn(t[x][y + i]);
}

// ---------------------------------------------------------------------------
// V transpose per group (fp32): V[g][s][d] -> VT[g][d][s]
// ---------------------------------------------------------------------------
__global__ __launch_bounds__(256) void vtranspose(
    const float* __restrict__ V, float* __restrict__ VT)
{
    __shared__ float t[32][33];
    const int g = blockIdx.z;
    const int s0 = blockIdx.x * 32, d0 = blockIdx.y * 32;
    const int x = threadIdx.x, y = threadIdx.y;   // 32 x 8
    const float* Vg = V + (size_t)g * SLEN * HEADDIM;
    float* VTg = VT + (size_t)g * SLEN * HEADDIM;
#pragma unroll
    for (int i = 0; i < 32; i += 8)
        t[y + i][x] = Vg[(size_t)(s0 + y + i) * HEADDIM + d0 + x];
    __syncthreads();
#pragma unroll
    for (int i = 0; i < 32; i += 8)
        VTg[(size_t)(d0 + y + i) * SLEN + s0 + x] = t[x][y + i];
}

// ---------------------------------------------------------------------------
// HMMA bf16 GEMM: C[M,N] = A[M,K] @ Bt[N,K]^T (+bias), fp32 accumulate/output.
// A, Bt row-major bf16 (K contiguous). blockIdx.z selects operand triple
// (batched Q/K/V projections in one launch).
// CTA 128x128, BK=64, 8 warps (4x2), warp 32x64 = 2x8 m16n8k16 tiles.
// Smem: [128 rows][36 words] per tile (72 bf16, 64 data + pad);
// fragment word addr = row*36 + s*8 + t -> banks (4g+t)%32 distinct.
// ---------------------------------------------------------------------------
#define KSW 36                      // smem row stride in 32-bit words
#define TILE_WORDS (128 * KSW)      // 4608 words = 18432 B

__global__ __launch_bounds__(256) void gemm_bf16(
    const __nv_bfloat16* __restrict__ A0, const __nv_bfloat16* __restrict__ A1,
    const __nv_bfloat16* __restrict__ A2,
    const __nv_bfloat16* __restrict__ B0, const __nv_bfloat16* __restrict__ B1,
    const __nv_bfloat16* __restrict__ B2,
    float* __restrict__ C0, float* __restrict__ C1, float* __restrict__ C2,
    const float* __restrict__ bias, int M, int N, int K)
{
    extern __shared__ uint32_t shw[];
    uint32_t* sA[2] = { shw,                  shw + 2 * TILE_WORDS };
    uint32_t* sB[2] = { shw + TILE_WORDS,     shw + 3 * TILE_WORDS };

    const int z = blockIdx.z;
    const __nv_bfloat16* A = (z == 0) ? A0 : (z == 1) ? A1 : A2;
    const __nv_bfloat16* Bt = (z == 0) ? B0 : (z == 1) ? B1 : B2;
    float* C = (z == 0) ? C0 : (z == 1) ? C1 : C2;

    const int tid = threadIdx.x;
    const int wid = tid >> 5;
    const int lane = tid & 31;
    const int mb = (wid & 3) * 32;
    const int nb = (wid >> 2) * 64;
    const int g = lane >> 2;
    const int t = lane & 3;
    const int m0 = blockIdx.y * 128;
    const int n0 = blockIdx.x * 128;

    float acc[2][8][4];
#pragma unroll
    for (int i = 0; i < 2; i++)
#pragma unroll
        for (int j = 0; j < 8; j++)
#pragma unroll
            for (int q = 0; q < 4; q++) acc[i][j][q] = 0.f;

    const int NCH = K / 64;

    // load chunk c (BK=64 bf16 = 128 B = 8 x 16B per row) into buffer b
    auto issue = [&](int c, int b) {
        const __nv_bfloat16* Ag = A + (size_t)m0 * K + (size_t)c * 64;
        const __nv_bfloat16* Bg = Bt + (size_t)n0 * K + (size_t)c * 64;
        const uint32_t sa = smem_u32(sA[b]);
        const uint32_t sb = smem_u32(sB[b]);
#pragma unroll
        for (int i = 0; i < 4; i++) {
            const int u = tid + 256 * i;       // 0..1023
            const int row = u >> 3;
            const int seg = u & 7;
            const uint32_t so = (uint32_t)(row * KSW + seg * 4) * 4u;
            cp_async16(sa + so, Ag + (size_t)row * K + seg * 8);
            cp_async16(sb + so, Bg + (size_t)row * K + seg * 8);
        }
        CP_COMMIT();
    };

    issue(0, 0);
    issue(1, 1);

    for (int c = 0; c < NCH; c++) {
        const int b = c & 1;
        CP_WAIT1();
        __syncthreads();

        const uint32_t* As_ = sA[b];
        const uint32_t* Bs_ = sB[b];
#pragma unroll
        for (int s = 0; s < 4; s++) {          // 4 k-steps of 16 elements
            const int k0w = s * 8;
            uint32_t af[2][4];
#pragma unroll
            for (int mt = 0; mt < 2; mt++) {
                const int r0 = mb + mt * 16 + g;
                af[mt][0] = As_[r0 * KSW + k0w + t];
                af[mt][1] = As_[(r0 + 8) * KSW + k0w + t];
                af[mt][2] = As_[r0 * KSW + k0w + t + 4];
                af[mt][3] = As_[(r0 + 8) * KSW + k0w + t + 4];
            }
#pragma unroll
            for (int nt = 0; nt < 8; nt++) {
                const int nr = nb + nt * 8 + g;
                uint32_t bf[2];
                bf[0] = Bs_[nr * KSW + k0w + t];
                bf[1] = Bs_[nr * KSW + k0w + t + 4];
                mma_bf16(acc[0][nt], af[0], bf);
                mma_bf16(acc[1][nt], af[1], bf);
            }
        }
        __syncthreads();
        if (c + 2 < NCH) issue(c + 2, b);
        else CP_COMMIT();   // keep wait_group accounting uniform
    }

#pragma unroll
    for (int mt = 0; mt < 2; mt++) {
        const int r = m0 + mb + mt * 16 + g;
#pragma unroll
        for (int nt = 0; nt < 8; nt++) {
            const int cx = n0 + nb + nt * 8 + 2 * t;
            float2 v0, v1;
            v0.x = acc[mt][nt][0]; v0.y = acc[mt][nt][1];
            v1.x = acc[mt][nt][2]; v1.y = acc[mt][nt][3];
            if (bias) {
                const float b0 = __ldg(&bias[cx]);
                const float b1 = __ldg(&bias[cx + 1]);
                v0.x += b0; v0.y += b1;
                v1.x += b0; v1.y += b1;
            }
            *(float2*)(C + (size_t)r * N + cx) = v0;
            *(float2*)(C + (size_t)(r + 8) * N + cx) = v1;
        }
    }
}

// ---------------------------------------------------------------------------
// HMMA tf32 flash attention (validated in R5). Q,K fp32 [32][2048][64];
// VT fp32 [32][64][2048]. Output now written as bf16 (feeds output GEMM).
// CTA: 128 Q rows x 1 group, 8 warps (16 rows each).
// ---------------------------------------------------------------------------
#define ATS 68   // attention smem row stride (words)

__global__ __launch_bounds__(256) void attn_mma(
    const float* __restrict__ Q, const float* __restrict__ K,
    const float* __restrict__ VT, const unsigned char* __restrict__ mask,
    __nv_bfloat16* __restrict__ O)
{
    extern __shared__ uint32_t smw[];
    uint32_t* sK  = smw;                 // [64][ATS]
    uint32_t* sVT = smw + 64 * ATS;      // [64][ATS]
    uint32_t* sP  = smw + 2 * 64 * ATS;  // [128][ATS]

    const int tid = threadIdx.x;
    const int wid = tid >> 5;            // 0..7
    const int lane = tid & 31;
    const int gq = lane >> 2;            // 0..7
    const int t = lane & 3;              // 0..3
    const int qb = blockIdx.x;           // 0..15
    const int grp = blockIdx.y;          // 0..31
    const int r0 = wid * 16;

    const float* Qg = Q + ((size_t)grp * SLEN + qb * 128 + r0) * HEADDIM;
    const float* Kg = K + (size_t)grp * SLEN * HEADDIM;
    const float* VTg = VT + (size_t)grp * SLEN * HEADDIM;
    const unsigned char* mrow =
        mask + (size_t)(grp % BATCH) * SLEN * SLEN + (size_t)(qb * 128 + r0) * SLEN;

    // ---- Stage Q (warp-private rows of sP), build persistent A fragments
    uint32_t* sQw = sP + r0 * ATS;
    {
        const int row = lane >> 1;           // 0..15
        const int cs = (lane & 1) * 32;      // 0 or 32
#pragma unroll
        for (int j = 0; j < 8; j++) {
            float4 v = *(const float4*)(Qg + row * HEADDIM + cs + j * 4);
            uint4 u;
            u.x = f2tf32(v.x); u.y = f2tf32(v.y);
            u.z = f2tf32(v.z); u.w = f2tf32(v.w);
            *(uint4*)&sQw[row * ATS + cs + j * 4] = u;
        }
    }
    __syncwarp();
    uint32_t qf[8][4];
#pragma unroll
    for (int ks = 0; ks < 8; ks++) {
        const int k0 = ks * 8;
        qf[ks][0] = sQw[gq * ATS + k0 + t];
        qf[ks][1] = sQw[(gq + 8) * ATS + k0 + t];
        qf[ks][2] = sQw[gq * ATS + k0 + t + 4];
        qf[ks][3] = sQw[(gq + 8) * ATS + k0 + t + 4];
    }
    __syncwarp();

    float oacc[8][4];
#pragma unroll
    for (int nt = 0; nt < 8; nt++)
#pragma unroll
        for (int q = 0; q < 4; q++) oacc[nt][q] = 0.f;
    float mA = -INFINITY, mB = -INFINITY, lA = 0.f, lB = 0.f;

    const float scale = 0.125f;   // 1/sqrt(64)
    uint32_t* sPw = sP + r0 * ATS;

    for (int kt = 0; kt < SLEN / 64; kt++) {
        __syncthreads();
        {
            const int row = tid >> 2;        // 0..63
            const int cs = (tid & 3) * 16;
            const float* Kp = Kg + (size_t)(kt * 64 + row) * HEADDIM + cs;
            const float* Vp = VTg + (size_t)row * SLEN + kt * 64 + cs;
#pragma unroll
            for (int j = 0; j < 4; j++) {
                float4 kv = *(const float4*)(Kp + j * 4);
                uint4 ku;
                ku.x = f2tf32(kv.x); ku.y = f2tf32(kv.y);
                ku.z = f2tf32(kv.z); ku.w = f2tf32(kv.w);
                *(uint4*)&sK[row * ATS + cs + j * 4] = ku;
                float4 vv = *(const float4*)(Vp + j * 4);
                uint4 vu;
                vu.x = f2tf32(vv.x); vu.y = f2tf32(vv.y);
                vu.z = f2tf32(vv.z); vu.w = f2tf32(vv.w);
                *(uint4*)&sVT[row * ATS + cs + j * 4] = vu;
            }
        }
        __syncthreads();

        // ---- S = Q K^T
        float sacc[8][4];
#pragma unroll
        for (int nt = 0; nt < 8; nt++)
#pragma unroll
            for (int q = 0; q < 4; q++) sacc[nt][q] = 0.f;
#pragma unroll
        for (int ks = 0; ks < 8; ks++) {
            const int k0 = ks * 8;
#pragma unroll
            for (int nt = 0; nt < 8; nt++) {
                uint32_t bf[2];
                bf[0] = sK[(nt * 8 + gq) * ATS + k0 + t];
                bf[1] = sK[(nt * 8 + gq) * ATS + k0 + t + 4];
                mma_tf32(sacc[nt], qf[ks], bf);
            }
        }

        // ---- Mask + scale
#pragma unroll
        for (int nt = 0; nt < 8; nt++) {
            const int cb = kt * 64 + nt * 8 + 2 * t;
            uchar2 ma = *(const uchar2*)(mrow + (size_t)gq * SLEN + cb);
            uchar2 mb2 = *(const uchar2*)(mrow + (size_t)(gq + 8) * SLEN + cb);
            sacc[nt][0] = ma.x ? -1e9f : sacc[nt][0] * scale;
            sacc[nt][1] = ma.y ? -1e9f : sacc[nt][1] * scale;
            sacc[nt][2] = mb2.x ? -1e9f : sacc[nt][2] * scale;
            sacc[nt][3] = mb2.y ? -1e9f : sacc[nt][3] * scale;
        }

        // ---- Online softmax
        float mxA = -INFINITY, mxB = -INFINITY;
#pragma unroll
        for (int nt = 0; nt < 8; nt++) {
            mxA = fmaxf(mxA, fmaxf(sacc[nt][0], sacc[nt][1]));
            mxB = fmaxf(mxB, fmaxf(sacc[nt][2], sacc[nt][3]));
        }
        mxA = fmaxf(mxA, __shfl_xor_sync(0xffffffffu, mxA, 1));
        mxA = fmaxf(mxA, __shfl_xor_sync(0xffffffffu, mxA, 2));
        mxB = fmaxf(mxB, __shfl_xor_sync(0xffffffffu, mxB, 1));
        mxB = fmaxf(mxB, __shfl_xor_sync(0xffffffffu, mxB, 2));

        const float mnA = fmaxf(mA, mxA);
        const float mnB = fmaxf(mB, mxB);
        const float cA = __expf(mA - mnA);
        const float cB = __expf(mB - mnB);
        float suA = 0.f, suB = 0.f;
#pragma unroll
        for (int nt = 0; nt < 8; nt++) {
            sacc[nt][0] = __expf(sacc[nt][0] - mnA);
            sacc[nt][1] = __expf(sacc[nt][1] - mnA);
            sacc[nt][2] = __expf(sacc[nt][2] - mnB);
            sacc[nt][3] = __expf(sacc[nt][3] - mnB);
            suA += sacc[nt][0] + sacc[nt][1];
            suB += sacc[nt][2] + sacc[nt][3];
        }
        suA += __shfl_xor_sync(0xffffffffu, suA, 1);
        suA += __shfl_xor_sync(0xffffffffu, suA, 2);
        suB += __shfl_xor_sync(0xffffffffu, suB, 1);
        suB += __shfl_xor_sync(0xffffffffu, suB, 2);
        lA = lA * cA + suA;
        lB = lB * cB + suB;
        mA = mnA;
        mB = mnB;
#pragma unroll
        for (int nt = 0; nt < 8; nt++) {
            oacc[nt][0] *= cA; oacc[nt][1] *= cA;
            oacc[nt][2] *= cB; oacc[nt][3] *= cB;
        }

        // ---- Stage P (tf32 bits) in warp-private smem rows
#pragma unroll
        for (int nt = 0; nt < 8; nt++) {
            const int cb = nt * 8 + 2 * t;
            sPw[gq * ATS + cb]       = f2tf32(sacc[nt][0]);
            sPw[gq * ATS + cb + 1]   = f2tf32(sacc[nt][1]);
            sPw[(gq + 8) * ATS + cb]     = f2tf32(sacc[nt][2]);
            sPw[(gq + 8) * ATS + cb + 1] = f2tf32(sacc[nt][3]);
        }
        __syncwarp();

        // ---- O += P V
#pragma unroll
        for (int ks = 0; ks < 8; ks++) {
            const int k0 = ks * 8;
            uint32_t af[4];
            af[0] = sPw[gq * ATS + k0 + t];
            af[1] = sPw[(gq + 8) * ATS + k0 + t];
            af[2] = sPw[gq * ATS + k0 + t + 4];
            af[3] = sPw[(gq + 8) * ATS + k0 + t + 4];
#pragma unroll
            for (int nt = 0; nt < 8; nt++) {
                uint32_t bf[2];
                bf[0] = sVT[(nt * 8 + gq) * ATS + k0 + t];
                bf[1] = sVT[(nt * 8 + gq) * ATS + k0 + t + 4];
                mma_tf32(oacc[nt], af, bf);
            }
        }
        __syncwarp();
    }

    // ---- Normalize + write O as bf16 (flat [32][2048][64])
    const float iA = 1.f / lA;
    const float iB = 1.f / lB;
    __nv_bfloat16* Og = O + ((size_t)grp * SLEN + qb * 128 + r0) * HEADDIM;
#pragma unroll
    for (int nt = 0; nt < 8; nt++) {
        const int cb = nt * 8 + 2 * t;   // even => 4B-aligned bf16x2 store
        __nv_bfloat162 hA = __floats2bfloat162_rn(oacc[nt][0] * iA, oacc[nt][1] * iA);
        __nv_bfloat162 hB = __floats2bfloat162_rn(oacc[nt][2] * iB, oacc[nt][3] * iB);
        *reinterpret_cast<__nv_bfloat162*>(Og + (size_t)gq * HEADDIM + cb) = hA;
        *reinterpret_cast<__nv_bfloat162*>(Og + (size_t)(gq + 8) * HEADDIM + cb) = hB;
    }
}

// ---------------------------------------------------------------------------
// Fused residual + LayerNorm (unchanged)
// ---------------------------------------------------------------------------
__global__ __launch_bounds__(256) void ln_kernel(
    const float* __restrict__ x, const float* __restrict__ p,
    const float* __restrict__ gamma, const float* __restrict__ beta,
    float* __restrict__ out)
{
    const int row = blockIdx.x;
    const int t = threadIdx.x;
    const size_t base = (size_t)row * DMODEL + t * 4;

    float4 xv = *(const float4*)(x + base);
    float4 pv = *(const float4*)(p + base);
    float v0 = xv.x + pv.x, v1 = xv.y + pv.y, v2 = xv.z + pv.z, v3 = xv.w + pv.w;

    __shared__ float red[8];
    float s = v0 + v1 + v2 + v3;
#pragma unroll
    for (int off = 16; off >= 1; off >>= 1) s += __shfl_xor_sync(0xffffffffu, s, off);
    if ((t & 31) == 0) red[t >> 5] = s;
    __syncthreads();
    float mu = (red[0] + red[1] + red[2] + red[3] +
                red[4] + red[5] + red[6] + red[7]) * (1.f / DMODEL);
    __syncthreads();

    float d0 = v0 - mu, d1 = v1 - mu, d2 = v2 - mu, d3 = v3 - mu;
    float q = d0 * d0 + d1 * d1 + d2 * d2 + d3 * d3;
#pragma unroll
    for (int off = 16; off >= 1; off >>= 1) q += __shfl_xor_sync(0xffffffffu, q, off);
    if ((t & 31) == 0) red[t >> 5] = q;
    __syncthreads();
    float var = (red[0] + red[1] + red[2] + red[3] +
                 red[4] + red[5] + red[6] + red[7]) * (1.f / DMODEL);
    float rs = rsqrtf(var + 1e-5f);

    float4 gv = *(const float4*)(gamma + t * 4);
    float4 bv = *(const float4*)(beta + t * 4);
    float4 ov;
    ov.x = d0 * rs * gv.x + bv.x;
    ov.y = d1 * rs * gv.y + bv.y;
    ov.z = d2 * rs * gv.z + bv.z;
    ov.w = d3 * rs * gv.w + bv.w;
    *(float4*)(out + base) = ov;
}

// ---------------------------------------------------------------------------
// Launch
// ---------------------------------------------------------------------------
extern "C" void kernel_launch(void* const* d_in, const int* in_sizes, int n_in,
                              void* d_out, int out_size)
{
    (void)in_sizes; (void)n_in; (void)out_size;
    const float* q_in  = (const float*)d_in[0];
    const float* k_in  = (const float*)d_in[1];
    const float* v_in  = (const float*)d_in[2];
    const unsigned char* mask = (const unsigned char*)d_in[3];
    const float* Wq = (const float*)d_in[4];
    const float* Wk = (const float*)d_in[5];
    const float* Wv = (const float*)d_in[6];
    const float* Wo = (const float*)d_in[7];
    const float* bo = (const float*)d_in[8];
    const float* gamma = (const float*)d_in[9];
    const float* beta  = (const float*)d_in[10];
    float* out = (float*)d_out;

    float *pQ, *pK, *pV, *pVT, *pP;
    __nv_bfloat16 *pOb, *pQin, *pKin, *pVin, *pWqT, *pWkT, *pWvT, *pWoT;
    cudaGetSymbolAddress((void**)&pQ, g_Q);
    cudaGetSymbolAddress((void**)&pK, g_K);
    cudaGetSymbolAddress((void**)&pV, g_V);
    cudaGetSymbolAddress((void**)&pVT, g_VT);
    cudaGetSymbolAddress((void**)&pP, g_P);
    cudaGetSymbolAddress((void**)&pOb, g_Ob);
    cudaGetSymbolAddress((void**)&pQin, g_Qin);
    cudaGetSymbolAddress((void**)&pKin, g_Kin);
    cudaGetSymbolAddress((void**)&pVin, g_Vin);
    cudaGetSymbolAddress((void**)&pWqT, g_WqT);
    cudaGetSymbolAddress((void**)&pWkT, g_WkT);
    cudaGetSymbolAddress((void**)&pWvT, g_WvT);
    cudaGetSymbolAddress((void**)&pWoT, g_WoT);

    const int gemm_smem = 4 * TILE_WORDS * (int)sizeof(uint32_t);   // 73728 B
    cudaFuncSetAttribute(gemm_bf16, cudaFuncAttributeMaxDynamicSharedMemorySize, gemm_smem);
    const int attn_smem = (2 * 64 * ATS + 128 * ATS) * (int)sizeof(uint32_t);  // 69632 B
    cudaFuncSetAttribute(attn_mma, cudaFuncAttributeMaxDynamicSharedMemorySize, attn_smem);

    // fp32 -> bf16 input copies
    const int cvt_blocks = NROWS * DMODEL / (256 * 8);   // 2048
    cvt_bf16<<<cvt_blocks, 256>>>(q_in, pQin);
    cvt_bf16<<<cvt_blocks, 256>>>(k_in, pKin);
    cvt_bf16<<<cvt_blocks, 256>>>(v_in, pVin);

    // transpose weights to [N, K] bf16
    dim3 tgrid(DMODEL / 32, DMODEL / 32);
    dim3 tblk(32, 8);
    transpose1024_bf16<<<tgrid, tblk>>>(Wq, pWqT);
    transpose1024_bf16<<<tgrid, tblk>>>(Wk, pWkT);
    transpose1024_bf16<<<tgrid, tblk>>>(Wv, pWvT);
    transpose1024_bf16<<<tgrid, tblk>>>(Wo, pWoT);

    // batched Q/K/V projections: one launch, z selects operands
    dim3 ggrid3(DMODEL / 128, NROWS / 128, 3);    // (8, 32, 3)
    gemm_bf16<<<ggrid3, 256, gemm_smem>>>(
        pQin, pKin, pVin, pWqT, pWkT, pWvT, pQ, pK, pV,
        nullptr, NROWS, DMODEL, DMODEL);

    // V -> VT per group
    dim3 vgrid(SLEN / 32, HEADDIM / 32, NGROUPS);
    vtranspose<<<vgrid, tblk>>>(pV, pVT);

    dim3 agrid(SLEN / 128, NGROUPS);              // (16, 32)
    attn_mma<<<agrid, 256, attn_smem>>>(pQ, pK, pVT, mask, pOb);

    // output projection (+bias)
    dim3 ggrid1(DMODEL / 128, NROWS / 128, 1);
    gemm_bf16<<<ggrid1, 256, gemm_smem>>>(
        pOb, pOb, pOb, pWoT, pWoT, pWoT, pP, pP, pP,
        bo, NROWS, DMODEL, DMODEL);

    ln_kernel<<<NROWS, 256>>>(q_in, pP, gamma, beta, out);
}

// round 7
// speedup vs baseline: 4.0005x; 1.2691x over previous
#include <cuda_runtime.h>
#include <cuda_bf16.h>
#include <math.h>
#include <cstdint>

// Problem constants
#define BATCH   2
#define SLEN    2048
#define DMODEL  1024
#define NHEADS  16
#define HEADDIM 64
#define NROWS   (BATCH * SLEN)      // 4096
#define NGROUPS (BATCH * NHEADS)    // 32 reshaped "heads"

// Scratch (allocation-free rule: __device__ globals)
__device__ float g_P[NROWS * DMODEL];
__device__ __nv_bfloat16 g_Qb[NROWS * DMODEL];   // projected Q (bf16)
__device__ __nv_bfloat16 g_Kb[NROWS * DMODEL];   // projected K (bf16)
__device__ __nv_bfloat16 g_Vb[NROWS * DMODEL];   // projected V (bf16)
__device__ __nv_bfloat16 g_VTb[NROWS * DMODEL];  // per-group transposed V (bf16)
__device__ __nv_bfloat16 g_Ob[NROWS * DMODEL];   // attention output (bf16)
__device__ __nv_bfloat16 g_Qin[NROWS * DMODEL];  // bf16 copies of inputs
__device__ __nv_bfloat16 g_Kin[NROWS * DMODEL];
__device__ __nv_bfloat16 g_Vin[NROWS * DMODEL];
__device__ __nv_bfloat16 g_WqT[DMODEL * DMODEL]; // bf16 transposed weights
__device__ __nv_bfloat16 g_WkT[DMODEL * DMODEL];
__device__ __nv_bfloat16 g_WvT[DMODEL * DMODEL];
__device__ __nv_bfloat16 g_WoT[DMODEL * DMODEL];

// ---------------------------------------------------------------------------
// Helpers (sm_80+ only — compute_103 rejects 'a'-gated PTX like tcgen05)
// ---------------------------------------------------------------------------
__device__ __forceinline__ uint32_t smem_u32(const void* p) {
    uint32_t a;
    asm("{ .reg .u64 t; cvta.to.shared.u64 t, %1; cvt.u32.u64 %0, t; }"
        : "=r"(a) : "l"(p));
    return a;
}

__device__ __forceinline__ void cp_async16(uint32_t saddr, const void* gaddr) {
    asm volatile("cp.async.cg.shared.global [%0], [%1], 16;"
                 :: "r"(saddr), "l"(gaddr) : "memory");
}
#define CP_COMMIT() asm volatile("cp.async.commit_group;" ::: "memory")
#define CP_WAIT1()  asm volatile("cp.async.wait_group 1;" ::: "memory")

__device__ __forceinline__ void mma_bf16(float* d, const uint32_t* a, const uint32_t* b) {
    asm volatile(
        "mma.sync.aligned.m16n8k16.row.col.f32.bf16.bf16.f32 "
        "{%0,%1,%2,%3}, {%4,%5,%6,%7}, {%8,%9}, {%0,%1,%2,%3};"
        : "+f"(d[0]), "+f"(d[1]), "+f"(d[2]), "+f"(d[3])
        : "r"(a[0]), "r"(a[1]), "r"(a[2]), "r"(a[3]), "r"(b[0]), "r"(b[1]));
}

__device__ __forceinline__ uint32_t pack_bf16x2(float lo, float hi) {
    __nv_bfloat162 h = __floats2bfloat162_rn(lo, hi);
    return *reinterpret_cast<uint32_t*>(&h);
}

// ---------------------------------------------------------------------------
// fp32 -> bf16 conversion (8 elements/thread)
// ---------------------------------------------------------------------------
__global__ __launch_bounds__(256) void cvt_bf16(
    const float* __restrict__ x, __nv_bfloat16* __restrict__ y)
{
    const size_t i = ((size_t)blockIdx.x * 256 + threadIdx.x) * 8;
    float4 a = *(const float4*)(x + i);
    float4 b = *(const float4*)(x + i + 4);
    __nv_bfloat162* yp = reinterpret_cast<__nv_bfloat162*>(y + i);
    yp[0] = __floats2bfloat162_rn(a.x, a.y);
    yp[1] = __floats2bfloat162_rn(a.z, a.w);
    yp[2] = __floats2bfloat162_rn(b.x, b.y);
    yp[3] = __floats2bfloat162_rn(b.z, b.w);
}

// ---------------------------------------------------------------------------
// Weight transpose (fp32 -> bf16): Wt[n][k] = bf16(W[k][n]), 1024x1024
// ---------------------------------------------------------------------------
__global__ __launch_bounds__(256) void transpose1024_bf16(
    const float* __restrict__ W, __nv_bfloat16* __restrict__ Wt)
{
    __shared__ float t[32][33];
    const int bx = blockIdx.x * 32, by = blockIdx.y * 32;
    const int x = threadIdx.x, y = threadIdx.y;   // 32 x 8
#pragma unroll
    for (int i = 0; i < 32; i += 8)
        t[y + i][x] = W[(size_t)(by + y + i) * DMODEL + bx + x];
    __syncthreads();
#pragma unroll
    for (int i = 0; i < 32; i += 8)
        Wt[(size_t)(bx + y + i) * DMODEL + by + x] = __float2bfloat16_rn(t[x][y + i]);
}

// ---------------------------------------------------------------------------
// V transpose per group (bf16): V[g][s][d] -> VT[g][d][s]
// ---------------------------------------------------------------------------
__global__ __launch_bounds__(256) void vtranspose_bf16(
    const __nv_bfloat16* __restrict__ V, __nv_bfloat16* __restrict__ VT)
{
    __shared__ __nv_bfloat16 t[32][34];   // stride 34 (17 words): gcd(17,32)=1
    const int g = blockIdx.z;
    const int s0 = blockIdx.x * 32, d0 = blockIdx.y * 32;
    const int x = threadIdx.x, y = threadIdx.y;   // 32 x 8
    const __nv_bfloat16* Vg = V + (size_t)g * SLEN * HEADDIM;
    __nv_bfloat16* VTg = VT + (size_t)g * SLEN * HEADDIM;
#pragma unroll
    for (int i = 0; i < 32; i += 8)
        t[y + i][x] = Vg[(size_t)(s0 + y + i) * HEADDIM + d0 + x];
    __syncthreads();
#pragma unroll
    for (int i = 0; i < 32; i += 8)
        VTg[(size_t)(d0 + y + i) * SLEN + s0 + x] = t[x][y + i];
}

// ---------------------------------------------------------------------------
// HMMA bf16 GEMM core: CTA 128x128, BK=64, 8 warps (4x2), warp 32x64.
// Smem rows [128][36 words]; fragment loads hit banks (4g+t)%32 distinct.
// Two epilogue variants: bf16 output (QKV proj) and fp32+bias (out proj).
// ---------------------------------------------------------------------------
#define KSW 36
#define TILE_WORDS (128 * KSW)

// Batched Q/K/V projection: z selects (A, Bt, C-bf16)
__global__ __launch_bounds__(256) void gemm_bf16_qkv(
    const __nv_bfloat16* __restrict__ A0, const __nv_bfloat16* __restrict__ A1,
    const __nv_bfloat16* __restrict__ A2,
    const __nv_bfloat16* __restrict__ B0, const __nv_bfloat16* __restrict__ B1,
    const __nv_bfloat16* __restrict__ B2,
    __nv_bfloat16* __restrict__ C0, __nv_bfloat16* __restrict__ C1,
    __nv_bfloat16* __restrict__ C2, int M, int N, int K)
{
    extern __shared__ uint32_t shw[];
    uint32_t* sA[2] = { shw,              shw + 2 * TILE_WORDS };
    uint32_t* sB[2] = { shw + TILE_WORDS, shw + 3 * TILE_WORDS };

    const int z = blockIdx.z;
    const __nv_bfloat16* A = (z == 0) ? A0 : (z == 1) ? A1 : A2;
    const __nv_bfloat16* Bt = (z == 0) ? B0 : (z == 1) ? B1 : B2;
    __nv_bfloat16* C = (z == 0) ? C0 : (z == 1) ? C1 : C2;

    const int tid = threadIdx.x;
    const int wid = tid >> 5;
    const int lane = tid & 31;
    const int mb = (wid & 3) * 32;
    const int nb = (wid >> 2) * 64;
    const int g = lane >> 2;
    const int t = lane & 3;
    const int m0 = blockIdx.y * 128;
    const int n0 = blockIdx.x * 128;

    float acc[2][8][4];
#pragma unroll
    for (int i = 0; i < 2; i++)
#pragma unroll
        for (int j = 0; j < 8; j++)
#pragma unroll
            for (int q = 0; q < 4; q++) acc[i][j][q] = 0.f;

    const int NCH = K / 64;

    auto issue = [&](int c, int b) {
        const __nv_bfloat16* Ag = A + (size_t)m0 * K + (size_t)c * 64;
        const __nv_bfloat16* Bg = Bt + (size_t)n0 * K + (size_t)c * 64;
        const uint32_t sa = smem_u32(sA[b]);
        const uint32_t sb = smem_u32(sB[b]);
#pragma unroll
        for (int i = 0; i < 4; i++) {
            const int u = tid + 256 * i;
            const int row = u >> 3;
            const int seg = u & 7;
            const uint32_t so = (uint32_t)(row * KSW + seg * 4) * 4u;
            cp_async16(sa + so, Ag + (size_t)row * K + seg * 8);
            cp_async16(sb + so, Bg + (size_t)row * K + seg * 8);
        }
        CP_COMMIT();
    };

    issue(0, 0);
    issue(1, 1);

    for (int c = 0; c < NCH; c++) {
        const int b = c & 1;
        CP_WAIT1();
        __syncthreads();
        const uint32_t* As_ = sA[b];
        const uint32_t* Bs_ = sB[b];
#pragma unroll
        for (int s = 0; s < 4; s++) {
            const int k0w = s * 8;
            uint32_t af[2][4];
#pragma unroll
            for (int mt = 0; mt < 2; mt++) {
                const int r0 = mb + mt * 16 + g;
                af[mt][0] = As_[r0 * KSW + k0w + t];
                af[mt][1] = As_[(r0 + 8) * KSW + k0w + t];
                af[mt][2] = As_[r0 * KSW + k0w + t + 4];
                af[mt][3] = As_[(r0 + 8) * KSW + k0w + t + 4];
            }
#pragma unroll
            for (int nt = 0; nt < 8; nt++) {
                const int nr = nb + nt * 8 + g;
                uint32_t bf[2];
                bf[0] = Bs_[nr * KSW + k0w + t];
                bf[1] = Bs_[nr * KSW + k0w + t + 4];
                mma_bf16(acc[0][nt], af[0], bf);
                mma_bf16(acc[1][nt], af[1], bf);
            }
        }
        __syncthreads();
        if (c + 2 < NCH) issue(c + 2, b);
        else CP_COMMIT();
    }

#pragma unroll
    for (int mt = 0; mt < 2; mt++) {
        const int r = m0 + mb + mt * 16 + g;
#pragma unroll
        for (int nt = 0; nt < 8; nt++) {
            const int cx = n0 + nb + nt * 8 + 2 * t;
            uint32_t w0 = pack_bf16x2(acc[mt][nt][0], acc[mt][nt][1]);
            uint32_t w1 = pack_bf16x2(acc[mt][nt][2], acc[mt][nt][3]);
            *reinterpret_cast<uint32_t*>(C + (size_t)r * N + cx) = w0;
            *reinterpret_cast<uint32_t*>(C + (size_t)(r + 8) * N + cx) = w1;
        }
    }
}

// Output projection: fp32 output + bias
__global__ __launch_bounds__(256) void gemm_bf16_out(
    const __nv_bfloat16* __restrict__ A, const __nv_bfloat16* __restrict__ Bt,
    const float* __restrict__ bias, float* __restrict__ C,
    int M, int N, int K)
{
    extern __shared__ uint32_t shw[];
    uint32_t* sA[2] = { shw,              shw + 2 * TILE_WORDS };
    uint32_t* sB[2] = { shw + TILE_WORDS, shw + 3 * TILE_WORDS };

    const int tid = threadIdx.x;
    const int wid = tid >> 5;
    const int lane = tid & 31;
    const int mb = (wid & 3) * 32;
    const int nb = (wid >> 2) * 64;
    const int g = lane >> 2;
    const int t = lane & 3;
    const int m0 = blockIdx.y * 128;
    const int n0 = blockIdx.x * 128;

    float acc[2][8][4];
#pragma unroll
    for (int i = 0; i < 2; i++)
#pragma unroll
        for (int j = 0; j < 8; j++)
#pragma unroll
            for (int q = 0; q < 4; q++) acc[i][j][q] = 0.f;

    const int NCH = K / 64;

    auto issue = [&](int c, int b) {
        const __nv_bfloat16* Ag = A + (size_t)m0 * K + (size_t)c * 64;
        const __nv_bfloat16* Bg = Bt + (size_t)n0 * K + (size_t)c * 64;
        const uint32_t sa = smem_u32(sA[b]);
        const uint32_t sb = smem_u32(sB[b]);
#pragma unroll
        for (int i = 0; i < 4; i++) {
            const int u = tid + 256 * i;
            const int row = u >> 3;
            const int seg = u & 7;
            const uint32_t so = (uint32_t)(row * KSW + seg * 4) * 4u;
            cp_async16(sa + so, Ag + (size_t)row * K + seg * 8);
            cp_async16(sb + so, Bg + (size_t)row * K + seg * 8);
        }
        CP_COMMIT();
    };

    issue(0, 0);
    issue(1, 1);

    for (int c = 0; c < NCH; c++) {
        const int b = c & 1;
        CP_WAIT1();
        __syncthreads();
        const uint32_t* As_ = sA[b];
        const uint32_t* Bs_ = sB[b];
#pragma unroll
        for (int s = 0; s < 4; s++) {
            const int k0w = s * 8;
            uint32_t af[2][4];
#pragma unroll
            for (int mt = 0; mt < 2; mt++) {
                const int r0 = mb + mt * 16 + g;
                af[mt][0] = As_[r0 * KSW + k0w + t];
                af[mt][1] = As_[(r0 + 8) * KSW + k0w + t];
                af[mt][2] = As_[r0 * KSW + k0w + t + 4];
                af[mt][3] = As_[(r0 + 8) * KSW + k0w + t + 4];
            }
#pragma unroll
            for (int nt = 0; nt < 8; nt++) {
                const int nr = nb + nt * 8 + g;
                uint32_t bf[2];
                bf[0] = Bs_[nr * KSW + k0w + t];
                bf[1] = Bs_[nr * KSW + k0w + t + 4];
                mma_bf16(acc[0][nt], af[0], bf);
                mma_bf16(acc[1][nt], af[1], bf);
            }
        }
        __syncthreads();
        if (c + 2 < NCH) issue(c + 2, b);
        else CP_COMMIT();
    }

#pragma unroll
    for (int mt = 0; mt < 2; mt++) {
        const int r = m0 + mb + mt * 16 + g;
#pragma unroll
        for (int nt = 0; nt < 8; nt++) {
            const int cx = n0 + nb + nt * 8 + 2 * t;
            const float b0 = __ldg(&bias[cx]);
            const float b1 = __ldg(&bias[cx + 1]);
            float2 v0, v1;
            v0.x = acc[mt][nt][0] + b0; v0.y = acc[mt][nt][1] + b1;
            v1.x = acc[mt][nt][2] + b0; v1.y = acc[mt][nt][3] + b1;
            *(float2*)(C + (size_t)r * N + cx) = v0;
            *(float2*)(C + (size_t)(r + 8) * N + cx) = v1;
        }
    }
}

// ---------------------------------------------------------------------------
// bf16 HMMA flash attention. Q,K bf16 [32][2048][64]; VT bf16 [32][64][2048].
// CTA: 128 Q rows x 1 group, 8 warps (16 rows each). K-tiles of 64 keys,
// double-buffered via cp.async. Smem rows 36 words (64 bf16 data + pad).
// ---------------------------------------------------------------------------
#define AKW 36   // words per smem row

__global__ __launch_bounds__(256) void attn_bf16(
    const __nv_bfloat16* __restrict__ Q, const __nv_bfloat16* __restrict__ K,
    const __nv_bfloat16* __restrict__ VT, const unsigned char* __restrict__ mask,
    __nv_bfloat16* __restrict__ O)
{
    extern __shared__ uint32_t smw[];
    uint32_t* sK[2]  = { smw,                smw + 64 * AKW };
    uint32_t* sVT[2] = { smw + 2 * 64 * AKW, smw + 3 * 64 * AKW };
    uint32_t* sP     = smw + 4 * 64 * AKW;   // [128][AKW]

    const int tid = threadIdx.x;
    const int wid = tid >> 5;            // 0..7
    const int lane = tid & 31;
    const int gq = lane >> 2;            // 0..7
    const int t = lane & 3;              // 0..3
    const int qb = blockIdx.x;           // 0..15
    const int grp = blockIdx.y;          // 0..31
    const int r0 = wid * 16;

    const __nv_bfloat16* Qg = Q + ((size_t)grp * SLEN + qb * 128 + r0) * HEADDIM;
    const __nv_bfloat16* Kg = K + (size_t)grp * SLEN * HEADDIM;
    const __nv_bfloat16* VTg = VT + (size_t)grp * SLEN * HEADDIM;
    const unsigned char* mrow =
        mask + (size_t)(grp % BATCH) * SLEN * SLEN + (size_t)(qb * 128 + r0) * SLEN;

    // issue cp.async loads of K/VT tile kt into buffer b
    auto issue = [&](int kt, int b) {
        const uint32_t sk = smem_u32(sK[b]);
        const uint32_t sv = smem_u32(sVT[b]);
#pragma unroll
        for (int i = 0; i < 2; i++) {
            const int u = tid + 256 * i;       // 0..511
            const int row = u >> 3;            // 0..63
            const int seg = u & 7;             // 0..7 (16B each)
            const uint32_t so = (uint32_t)(row * AKW + seg * 4) * 4u;
            cp_async16(sk + so, Kg + (size_t)(kt * 64 + row) * HEADDIM + seg * 8);
            cp_async16(sv + so, VTg + (size_t)row * SLEN + kt * 64 + seg * 8);
        }
        CP_COMMIT();
    };

    // ---- Stage Q (warp-private rows of sP), build persistent A fragments
    uint32_t* sQw = sP + r0 * AKW;
    {
        const int row = lane >> 1;           // 0..15
        const int cs = (lane & 1) * 16;      // word offset 0 or 16
#pragma unroll
        for (int j = 0; j < 4; j++) {
            uint4 v = *(const uint4*)(Qg + (size_t)row * HEADDIM + (cs + j * 4) * 2);
            *(uint4*)&sQw[row * AKW + cs + j * 4] = v;
        }
    }
    __syncwarp();
    uint32_t qf[4][4];
#pragma unroll
    for (int s = 0; s < 4; s++) {
        const int k0 = s * 8;
        qf[s][0] = sQw[gq * AKW + k0 + t];
        qf[s][1] = sQw[(gq + 8) * AKW + k0 + t];
        qf[s][2] = sQw[gq * AKW + k0 + t + 4];
        qf[s][3] = sQw[(gq + 8) * AKW + k0 + t + 4];
    }
    __syncthreads();   // Q fragments captured before sP reused for P

    issue(0, 0);
    issue(1, 1);

    float oacc[8][4];
#pragma unroll
    for (int nt = 0; nt < 8; nt++)
#pragma unroll
        for (int q = 0; q < 4; q++) oacc[nt][q] = 0.f;
    float mA = -INFINITY, mB = -INFINITY, lA = 0.f, lB = 0.f;

    const float scale = 0.125f;   // 1/sqrt(64)
    uint32_t* sPw = sP + r0 * AKW;
    const int NT = SLEN / 64;

    for (int kt = 0; kt < NT; kt++) {
        const int b = kt & 1;
        CP_WAIT1();
        __syncthreads();
        const uint32_t* sKb = sK[b];
        const uint32_t* sVb = sVT[b];

        // ---- S = Q K^T  (m16 x n64, K=64: 4 k-steps of 16)
        float sacc[8][4];
#pragma unroll
        for (int nt = 0; nt < 8; nt++)
#pragma unroll
            for (int q = 0; q < 4; q++) sacc[nt][q] = 0.f;
#pragma unroll
        for (int s = 0; s < 4; s++) {
            const int k0 = s * 8;
#pragma unroll
            for (int nt = 0; nt < 8; nt++) {
                uint32_t bf[2];
                bf[0] = sKb[(nt * 8 + gq) * AKW + k0 + t];
                bf[1] = sKb[(nt * 8 + gq) * AKW + k0 + t + 4];
                mma_bf16(sacc[nt], qf[s], bf);
            }
        }

        // ---- Mask + scale
#pragma unroll
        for (int nt = 0; nt < 8; nt++) {
            const int cb = kt * 64 + nt * 8 + 2 * t;
            uchar2 ma = *(const uchar2*)(mrow + (size_t)gq * SLEN + cb);
            uchar2 mb2 = *(const uchar2*)(mrow + (size_t)(gq + 8) * SLEN + cb);
            sacc[nt][0] = ma.x ? -1e9f : sacc[nt][0] * scale;
            sacc[nt][1] = ma.y ? -1e9f : sacc[nt][1] * scale;
            sacc[nt][2] = mb2.x ? -1e9f : sacc[nt][2] * scale;
            sacc[nt][3] = mb2.y ? -1e9f : sacc[nt][3] * scale;
        }

        // ---- Online softmax (rows gq / gq+8; reduce over 4-lane t-group)
        float mxA = -INFINITY, mxB = -INFINITY;
#pragma unroll
        for (int nt = 0; nt < 8; nt++) {
            mxA = fmaxf(mxA, fmaxf(sacc[nt][0], sacc[nt][1]));
            mxB = fmaxf(mxB, fmaxf(sacc[nt][2], sacc[nt][3]));
        }
        mxA = fmaxf(mxA, __shfl_xor_sync(0xffffffffu, mxA, 1));
        mxA = fmaxf(mxA, __shfl_xor_sync(0xffffffffu, mxA, 2));
        mxB = fmaxf(mxB, __shfl_xor_sync(0xffffffffu, mxB, 1));
        mxB = fmaxf(mxB, __shfl_xor_sync(0xffffffffu, mxB, 2));

        const float mnA = fmaxf(mA, mxA);
        const float mnB = fmaxf(mB, mxB);
        const float cA = __expf(mA - mnA);
        const float cB = __expf(mB - mnB);
        float suA = 0.f, suB = 0.f;
#pragma unroll
        for (int nt = 0; nt < 8; nt++) {
            sacc[nt][0] = __expf(sacc[nt][0] - mnA);
            sacc[nt][1] = __expf(sacc[nt][1] - mnA);
            sacc[nt][2] = __expf(sacc[nt][2] - mnB);
            sacc[nt][3] = __expf(sacc[nt][3] - mnB);
            suA += sacc[nt][0] + sacc[nt][1];
            suB += sacc[nt][2] + sacc[nt][3];
        }
        suA += __shfl_xor_sync(0xffffffffu, suA, 1);
        suA += __shfl_xor_sync(0xffffffffu, suA, 2);
        suB += __shfl_xor_sync(0xffffffffu, suB, 1);
        suB += __shfl_xor_sync(0xffffffffu, suB, 2);
        lA = lA * cA + suA;
        lB = lB * cB + suB;
        mA = mnA;
        mB = mnB;
#pragma unroll
        for (int nt = 0; nt < 8; nt++) {
            oacc[nt][0] *= cA; oacc[nt][1] *= cA;
            oacc[nt][2] *= cB; oacc[nt][3] *= cB;
        }

        // ---- Stage P packed bf16x2 (warp-private rows)
#pragma unroll
        for (int nt = 0; nt < 8; nt++) {
            sPw[gq * AKW + nt * 4 + t]       = pack_bf16x2(sacc[nt][0], sacc[nt][1]);
            sPw[(gq + 8) * AKW + nt * 4 + t] = pack_bf16x2(sacc[nt][2], sacc[nt][3]);
        }
        __syncwarp();

        // ---- O += P V  (k = 64 keys: 4 k-steps of 16; n = 64 dims)
#pragma unroll
        for (int s = 0; s < 4; s++) {
            const int k0 = s * 8;
            uint32_t af[4];
            af[0] = sPw[gq * AKW + k0 + t];
            af[1] = sPw[(gq + 8) * AKW + k0 + t];
            af[2] = sPw[gq * AKW + k0 + t + 4];
            af[3] = sPw[(gq + 8) * AKW + k0 + t + 4];
#pragma unroll
            for (int nt = 0; nt < 8; nt++) {
                uint32_t bf[2];
                bf[0] = sVb[(nt * 8 + gq) * AKW + k0 + t];
                bf[1] = sVb[(nt * 8 + gq) * AKW + k0 + t + 4];
                mma_bf16(oacc[nt], af, bf);
            }
        }
        __syncthreads();   // all warps done with buffer b before refill
        if (kt + 2 < NT) issue(kt + 2, b);
        else CP_COMMIT();
    }

    // ---- Normalize + write O as bf16 (flat [32][2048][64])
    const float iA = 1.f / lA;
    const float iB = 1.f / lB;
    __nv_bfloat16* Og = O + ((size_t)grp * SLEN + qb * 128 + r0) * HEADDIM;
#pragma unroll
    for (int nt = 0; nt < 8; nt++) {
        const int cb = nt * 8 + 2 * t;
        uint32_t wA = pack_bf16x2(oacc[nt][0] * iA, oacc[nt][1] * iA);
        uint32_t wB = pack_bf16x2(oacc[nt][2] * iB, oacc[nt][3] * iB);
        *reinterpret_cast<uint32_t*>(Og + (size_t)gq * HEADDIM + cb) = wA;
        *reinterpret_cast<uint32_t*>(Og + (size_t)(gq + 8) * HEADDIM + cb) = wB;
    }
}

// ---------------------------------------------------------------------------
// Fused residual + LayerNorm (unchanged)
// ---------------------------------------------------------------------------
__global__ __launch_bounds__(256) void ln_kernel(
    const float* __restrict__ x, const float* __restrict__ p,
    const float* __restrict__ gamma, const float* __restrict__ beta,
    float* __restrict__ out)
{
    const int row = blockIdx.x;
    const int t = threadIdx.x;
    const size_t base = (size_t)row * DMODEL + t * 4;

    float4 xv = *(const float4*)(x + base);
    float4 pv = *(const float4*)(p + base);
    float v0 = xv.x + pv.x, v1 = xv.y + pv.y, v2 = xv.z + pv.z, v3 = xv.w + pv.w;

    __shared__ float red[8];
    float s = v0 + v1 + v2 + v3;
#pragma unroll
    for (int off = 16; off >= 1; off >>= 1) s += __shfl_xor_sync(0xffffffffu, s, off);
    if ((t & 31) == 0) red[t >> 5] = s;
    __syncthreads();
    float mu = (red[0] + red[1] + red[2] + red[3] +
                red[4] + red[5] + red[6] + red[7]) * (1.f / DMODEL);
    __syncthreads();

    float d0 = v0 - mu, d1 = v1 - mu, d2 = v2 - mu, d3 = v3 - mu;
    float q = d0 * d0 + d1 * d1 + d2 * d2 + d3 * d3;
#pragma unroll
    for (int off = 16; off >= 1; off >>= 1) q += __shfl_xor_sync(0xffffffffu, q, off);
    if ((t & 31) == 0) red[t >> 5] = q;
    __syncthreads();
    float var = (red[0] + red[1] + red[2] + red[3] +
                 red[4] + red[5] + red[6] + red[7]) * (1.f / DMODEL);
    float rs = rsqrtf(var + 1e-5f);

    float4 gv = *(const float4*)(gamma + t * 4);
    float4 bv = *(const float4*)(beta + t * 4);
    float4 ov;
    ov.x = d0 * rs * gv.x + bv.x;
    ov.y = d1 * rs * gv.y + bv.y;
    ov.z = d2 * rs * gv.z + bv.z;
    ov.w = d3 * rs * gv.w + bv.w;
    *(float4*)(out + base) = ov;
}

// ---------------------------------------------------------------------------
// Launch
// ---------------------------------------------------------------------------
extern "C" void kernel_launch(void* const* d_in, const int* in_sizes, int n_in,
                              void* d_out, int out_size)
{
    (void)in_sizes; (void)n_in; (void)out_size;
    const float* q_in  = (const float*)d_in[0];
    const float* k_in  = (const float*)d_in[1];
    const float* v_in  = (const float*)d_in[2];
    const unsigned char* mask = (const unsigned char*)d_in[3];
    const float* Wq = (const float*)d_in[4];
    const float* Wk = (const float*)d_in[5];
    const float* Wv = (const float*)d_in[6];
    const float* Wo = (const float*)d_in[7];
    const float* bo = (const float*)d_in[8];
    const float* gamma = (const float*)d_in[9];
    const float* beta  = (const float*)d_in[10];
    float* out = (float*)d_out;

    float* pP;
    __nv_bfloat16 *pQb, *pKb, *pVb, *pVTb, *pOb, *pQin, *pKin, *pVin;
    __nv_bfloat16 *pWqT, *pWkT, *pWvT, *pWoT;
    cudaGetSymbolAddress((void**)&pP, g_P);
    cudaGetSymbolAddress((void**)&pQb, g_Qb);
    cudaGetSymbolAddress((void**)&pKb, g_Kb);
    cudaGetSymbolAddress((void**)&pVb, g_Vb);
    cudaGetSymbolAddress((void**)&pVTb, g_VTb);
    cudaGetSymbolAddress((void**)&pOb, g_Ob);
    cudaGetSymbolAddress((void**)&pQin, g_Qin);
    cudaGetSymbolAddress((void**)&pKin, g_Kin);
    cudaGetSymbolAddress((void**)&pVin, g_Vin);
    cudaGetSymbolAddress((void**)&pWqT, g_WqT);
    cudaGetSymbolAddress((void**)&pWkT, g_WkT);
    cudaGetSymbolAddress((void**)&pWvT, g_WvT);
    cudaGetSymbolAddress((void**)&pWoT, g_WoT);

    const int gemm_smem = 4 * TILE_WORDS * (int)sizeof(uint32_t);   // 73728 B
    cudaFuncSetAttribute(gemm_bf16_qkv, cudaFuncAttributeMaxDynamicSharedMemorySize, gemm_smem);
    cudaFuncSetAttribute(gemm_bf16_out, cudaFuncAttributeMaxDynamicSharedMemorySize, gemm_smem);
    const int attn_smem = (4 * 64 * AKW + 128 * AKW) * (int)sizeof(uint32_t);  // 55296 B
    cudaFuncSetAttribute(attn_bf16, cudaFuncAttributeMaxDynamicSharedMemorySize, attn_smem);

    // fp32 -> bf16 input copies
    const int cvt_blocks = NROWS * DMODEL / (256 * 8);   // 2048
    cvt_bf16<<<cvt_blocks, 256>>>(q_in, pQin);
    cvt_bf16<<<cvt_blocks, 256>>>(k_in, pKin);
    cvt_bf16<<<cvt_blocks, 256>>>(v_in, pVin);

    // transpose weights to [N, K] bf16
    dim3 tgrid(DMODEL / 32, DMODEL / 32);
    dim3 tblk(32, 8);
    transpose1024_bf16<<<tgrid, tblk>>>(Wq, pWqT);
    transpose1024_bf16<<<tgrid, tblk>>>(Wk, pWkT);
    transpose1024_bf16<<<tgrid, tblk>>>(Wv, pWvT);
    transpose1024_bf16<<<tgrid, tblk>>>(Wo, pWoT);

    // batched Q/K/V projections (bf16 out)
    dim3 ggrid3(DMODEL / 128, NROWS / 128, 3);
    gemm_bf16_qkv<<<ggrid3, 256, gemm_smem>>>(
        pQin, pKin, pVin, pWqT, pWkT, pWvT, pQb, pKb, pVb,
        NROWS, DMODEL, DMODEL);

    // V -> VT per group (bf16)
    dim3 vgrid(SLEN / 32, HEADDIM / 32, NGROUPS);
    vtranspose_bf16<<<vgrid, tblk>>>(pVb, pVTb);

    dim3 agrid(SLEN / 128, NGROUPS);              // (16, 32)
    attn_bf16<<<agrid, 256, attn_smem>>>(pQb, pKb, pVTb, mask, pOb);

    // output projection (+bias, fp32 out)
    dim3 ggrid1(DMODEL / 128, NROWS / 128);
    gemm_bf16_out<<<ggrid1, 256, gemm_smem>>>(pOb, pWoT, bo, pP, NROWS, DMODEL, DMODEL);

    ln_kernel<<<NROWS, 256>>>(q_in, pP, gamma, beta, out);
}

// round 8
// speedup vs baseline: 5.0047x; 1.2510x over previous
#include <cuda_runtime.h>
#include <cuda_bf16.h>
#include <math.h>
#include <cstdint>

// Problem constants
#define BATCH   2
#define SLEN    2048
#define DMODEL  1024
#define NHEADS  16
#define HEADDIM 64
#define NROWS   (BATCH * SLEN)      // 4096
#define NGROUPS (BATCH * NHEADS)    // 32 reshaped "heads"

// Scratch (allocation-free rule: __device__ globals)
__device__ float g_P[NROWS * DMODEL];
__device__ __nv_bfloat16 g_Qb[NROWS * DMODEL];
__device__ __nv_bfloat16 g_Kb[NROWS * DMODEL];
__device__ __nv_bfloat16 g_Vb[NROWS * DMODEL];
__device__ __nv_bfloat16 g_VTb[NROWS * DMODEL];
__device__ __nv_bfloat16 g_Ob[NROWS * DMODEL];
__device__ __nv_bfloat16 g_Qin[NROWS * DMODEL];
__device__ __nv_bfloat16 g_Kin[NROWS * DMODEL];
__device__ __nv_bfloat16 g_Vin[NROWS * DMODEL];
__device__ __nv_bfloat16 g_WqT[DMODEL * DMODEL];
__device__ __nv_bfloat16 g_WkT[DMODEL * DMODEL];
__device__ __nv_bfloat16 g_WvT[DMODEL * DMODEL];
__device__ __nv_bfloat16 g_WoT[DMODEL * DMODEL];

// ---------------------------------------------------------------------------
// Helpers (sm_80+ only — compute_103 rejects 'a'-gated PTX like tcgen05)
// ---------------------------------------------------------------------------
__device__ __forceinline__ uint32_t smem_u32(const void* p) {
    uint32_t a;
    asm("{ .reg .u64 t; cvta.to.shared.u64 t, %1; cvt.u32.u64 %0, t; }"
        : "=r"(a) : "l"(p));
    return a;
}

__device__ __forceinline__ void cp_async16(uint32_t saddr, const void* gaddr) {
    asm volatile("cp.async.cg.shared.global [%0], [%1], 16;"
                 :: "r"(saddr), "l"(gaddr) : "memory");
}
#define CP_COMMIT() asm volatile("cp.async.commit_group;" ::: "memory")
#define CP_WAIT1()  asm volatile("cp.async.wait_group 1;" ::: "memory")

__device__ __forceinline__ void mma_bf16(float* d, const uint32_t* a, const uint32_t* b) {
    asm volatile(
        "mma.sync.aligned.m16n8k16.row.col.f32.bf16.bf16.f32 "
        "{%0,%1,%2,%3}, {%4,%5,%6,%7}, {%8,%9}, {%0,%1,%2,%3};"
        : "+f"(d[0]), "+f"(d[1]), "+f"(d[2]), "+f"(d[3])
        : "r"(a[0]), "r"(a[1]), "r"(a[2]), "r"(a[3]), "r"(b[0]), "r"(b[1]));
}

__device__ __forceinline__ void ldsm_x4(uint32_t* r, uint32_t saddr) {
    asm volatile("ldmatrix.sync.aligned.m8n8.x4.shared.b16 {%0,%1,%2,%3}, [%4];"
                 : "=r"(r[0]), "=r"(r[1]), "=r"(r[2]), "=r"(r[3]) : "r"(saddr));
}

__device__ __forceinline__ uint32_t pack_bf16x2(float lo, float hi) {
    __nv_bfloat162 h = __floats2bfloat162_rn(lo, hi);
    return *reinterpret_cast<uint32_t*>(&h);
}

// ---------------------------------------------------------------------------
// fp32 -> bf16 conversion (8 elements/thread)
// ---------------------------------------------------------------------------
__global__ __launch_bounds__(256) void cvt_bf16(
    const float* __restrict__ x, __nv_bfloat16* __restrict__ y)
{
    const size_t i = ((size_t)blockIdx.x * 256 + threadIdx.x) * 8;
    float4 a = *(const float4*)(x + i);
    float4 b = *(const float4*)(x + i + 4);
    __nv_bfloat162* yp = reinterpret_cast<__nv_bfloat162*>(y + i);
    yp[0] = __floats2bfloat162_rn(a.x, a.y);
    yp[1] = __floats2bfloat162_rn(a.z, a.w);
    yp[2] = __floats2bfloat162_rn(b.x, b.y);
    yp[3] = __floats2bfloat162_rn(b.z, b.w);
}

// ---------------------------------------------------------------------------
// Weight transpose (fp32 -> bf16): Wt[n][k] = bf16(W[k][n]), 1024x1024
// ---------------------------------------------------------------------------
__global__ __launch_bounds__(256) void transpose1024_bf16(
    const float* __restrict__ W, __nv_bfloat16* __restrict__ Wt)
{
    __shared__ float t[32][33];
    const int bx = blockIdx.x * 32, by = blockIdx.y * 32;
    const int x = threadIdx.x, y = threadIdx.y;   // 32 x 8
#pragma unroll
    for (int i = 0; i < 32; i += 8)
        t[y + i][x] = W[(size_t)(by + y + i) * DMODEL + bx + x];
    __syncthreads();
#pragma unroll
    for (int i = 0; i < 32; i += 8)
        Wt[(size_t)(bx + y + i) * DMODEL + by + x] = __float2bfloat16_rn(t[x][y + i]);
}

// ---------------------------------------------------------------------------
// V transpose per group (bf16): V[g][s][d] -> VT[g][d][s]
// ---------------------------------------------------------------------------
__global__ __launch_bounds__(256) void vtranspose_bf16(
    const __nv_bfloat16* __restrict__ V, __nv_bfloat16* __restrict__ VT)
{
    __shared__ __nv_bfloat16 t[32][34];
    const int g = blockIdx.z;
    const int s0 = blockIdx.x * 32, d0 = blockIdx.y * 32;
    const int x = threadIdx.x, y = threadIdx.y;   // 32 x 8
    const __nv_bfloat16* Vg = V + (size_t)g * SLEN * HEADDIM;
    __nv_bfloat16* VTg = VT + (size_t)g * SLEN * HEADDIM;
#pragma unroll
    for (int i = 0; i < 32; i += 8)
        t[y + i][x] = Vg[(size_t)(s0 + y + i) * HEADDIM + d0 + x];
    __syncthreads();
#pragma unroll
    for (int i = 0; i < 32; i += 8)
        VTg[(size_t)(d0 + y + i) * SLEN + s0 + x] = t[x][y + i];
}

// ---------------------------------------------------------------------------
// HMMA bf16 GEMM core: CTA 128x128, BK=64, 8 warps (4x2), warp 32x64.
// Smem rows [128][36 words]; ldmatrix phases read 8 rows whose start banks
// are 4r mod 32 (4 banks/row) -> all 32 banks hit exactly once: conflict-free.
// ---------------------------------------------------------------------------
#define KSW 36
#define TILE_WORDS (128 * KSW)

// Shared mainloop body via macro-free duplication (two epilogues).
// Batched Q/K/V projection: z selects (A, Bt, C-bf16)
__global__ __launch_bounds__(256) void gemm_bf16_qkv(
    const __nv_bfloat16* __restrict__ A0, const __nv_bfloat16* __restrict__ A1,
    const __nv_bfloat16* __restrict__ A2,
    const __nv_bfloat16* __restrict__ B0, const __nv_bfloat16* __restrict__ B1,
    const __nv_bfloat16* __restrict__ B2,
    __nv_bfloat16* __restrict__ C0, __nv_bfloat16* __restrict__ C1,
    __nv_bfloat16* __restrict__ C2, int M, int N, int K)
{
    extern __shared__ uint32_t shw[];
    uint32_t* sA[2] = { shw,              shw + 2 * TILE_WORDS };
    uint32_t* sB[2] = { shw + TILE_WORDS, shw + 3 * TILE_WORDS };

    const int z = blockIdx.z;
    const __nv_bfloat16* A = (z == 0) ? A0 : (z == 1) ? A1 : A2;
    const __nv_bfloat16* Bt = (z == 0) ? B0 : (z == 1) ? B1 : B2;
    __nv_bfloat16* C = (z == 0) ? C0 : (z == 1) ? C1 : C2;

    const int tid = threadIdx.x;
    const int wid = tid >> 5;
    const int lane = tid & 31;
    const int mb = (wid & 3) * 32;
    const int nb = (wid >> 2) * 64;
    const int g = lane >> 2;
    const int t = lane & 3;
    const int m0 = blockIdx.y * 128;
    const int n0 = blockIdx.x * 128;

    // ldmatrix lane->address mapping
    const int quad = lane >> 3;
    const int within = lane & 7;
    const int arow = (quad & 1) * 8 + within;   // A: quads {r0-7@k0, r8-15@k0, r0-7@k4, r8-15@k4}
    const int acol = (quad >> 1) * 4;
    const int brow = (quad >> 1) * 8 + within;  // B: quads {n0-7@k0, n0-7@k4, n8-15@k0, n8-15@k4}
    const int bcol = (quad & 1) * 4;

    const uint32_t aoff0 = (uint32_t)((mb + arow) * KSW + acol) * 4u;
    const uint32_t aoff1 = (uint32_t)((mb + 16 + arow) * KSW + acol) * 4u;
    uint32_t boff[4];
#pragma unroll
    for (int ntp = 0; ntp < 4; ntp++)
        boff[ntp] = (uint32_t)((nb + ntp * 16 + brow) * KSW + bcol) * 4u;

    const uint32_t saw[2] = { smem_u32(sA[0]), smem_u32(sA[1]) };
    const uint32_t sbw[2] = { smem_u32(sB[0]), smem_u32(sB[1]) };

    float acc[2][8][4];
#pragma unroll
    for (int i = 0; i < 2; i++)
#pragma unroll
        for (int j = 0; j < 8; j++)
#pragma unroll
            for (int q = 0; q < 4; q++) acc[i][j][q] = 0.f;

    const int NCH = K / 64;

    auto issue = [&](int c, int b) {
        const __nv_bfloat16* Ag = A + (size_t)m0 * K + (size_t)c * 64;
        const __nv_bfloat16* Bg = Bt + (size_t)n0 * K + (size_t)c * 64;
#pragma unroll
        for (int i = 0; i < 4; i++) {
            const int u = tid + 256 * i;
            const int row = u >> 3;
            const int seg = u & 7;
            const uint32_t so = (uint32_t)(row * KSW + seg * 4) * 4u;
            cp_async16(saw[b] + so, Ag + (size_t)row * K + seg * 8);
            cp_async16(sbw[b] + so, Bg + (size_t)row * K + seg * 8);
        }
        CP_COMMIT();
    };

    issue(0, 0);
    issue(1, 1);

    for (int c = 0; c < NCH; c++) {
        const int b = c & 1;
        CP_WAIT1();
        __syncthreads();
#pragma unroll
        for (int s = 0; s < 4; s++) {
            const uint32_t ks = (uint32_t)s * 32u;   // s*8 words
            uint32_t af0[4], af1[4];
            ldsm_x4(af0, saw[b] + aoff0 + ks);
            ldsm_x4(af1, saw[b] + aoff1 + ks);
#pragma unroll
            for (int ntp = 0; ntp < 4; ntp++) {
                uint32_t bq[4];
                ldsm_x4(bq, sbw[b] + boff[ntp] + ks);
                mma_bf16(acc[0][2 * ntp],     af0, bq);
                mma_bf16(acc[1][2 * ntp],     af1, bq);
                mma_bf16(acc[0][2 * ntp + 1], af0, bq + 2);
                mma_bf16(acc[1][2 * ntp + 1], af1, bq + 2);
            }
        }
        __syncthreads();
        if (c + 2 < NCH) issue(c + 2, b);
        else CP_COMMIT();
    }

#pragma unroll
    for (int mt = 0; mt < 2; mt++) {
        const int r = m0 + mb + mt * 16 + g;
#pragma unroll
        for (int nt = 0; nt < 8; nt++) {
            const int cx = n0 + nb + nt * 8 + 2 * t;
            uint32_t w0 = pack_bf16x2(acc[mt][nt][0], acc[mt][nt][1]);
            uint32_t w1 = pack_bf16x2(acc[mt][nt][2], acc[mt][nt][3]);
            *reinterpret_cast<uint32_t*>(C + (size_t)r * N + cx) = w0;
            *reinterpret_cast<uint32_t*>(C + (size_t)(r + 8) * N + cx) = w1;
        }
    }
}

// Output projection: fp32 output + bias
__global__ __launch_bounds__(256) void gemm_bf16_out(
    const __nv_bfloat16* __restrict__ A, const __nv_bfloat16* __restrict__ Bt,
    const float* __restrict__ bias, float* __restrict__ C,
    int M, int N, int K)
{
    extern __shared__ uint32_t shw[];
    uint32_t* sA[2] = { shw,              shw + 2 * TILE_WORDS };
    uint32_t* sB[2] = { shw + TILE_WORDS, shw + 3 * TILE_WORDS };

    const int tid = threadIdx.x;
    const int wid = tid >> 5;
    const int lane = tid & 31;
    const int mb = (wid & 3) * 32;
    const int nb = (wid >> 2) * 64;
    const int g = lane >> 2;
    const int t = lane & 3;
    const int m0 = blockIdx.y * 128;
    const int n0 = blockIdx.x * 128;

    const int quad = lane >> 3;
    const int within = lane & 7;
    const int arow = (quad & 1) * 8 + within;
    const int acol = (quad >> 1) * 4;
    const int brow = (quad >> 1) * 8 + within;
    const int bcol = (quad & 1) * 4;

    const uint32_t aoff0 = (uint32_t)((mb + arow) * KSW + acol) * 4u;
    const uint32_t aoff1 = (uint32_t)((mb + 16 + arow) * KSW + acol) * 4u;
    uint32_t boff[4];
#pragma unroll
    for (int ntp = 0; ntp < 4; ntp++)
        boff[ntp] = (uint32_t)((nb + ntp * 16 + brow) * KSW + bcol) * 4u;

    const uint32_t saw[2] = { smem_u32(sA[0]), smem_u32(sA[1]) };
    const uint32_t sbw[2] = { smem_u32(sB[0]), smem_u32(sB[1]) };

    float acc[2][8][4];
#pragma unroll
    for (int i = 0; i < 2; i++)
#pragma unroll
        for (int j = 0; j < 8; j++)
#pragma unroll
            for (int q = 0; q < 4; q++) acc[i][j][q] = 0.f;

    const int NCH = K / 64;

    auto issue = [&](int c, int b) {
        const __nv_bfloat16* Ag = A + (size_t)m0 * K + (size_t)c * 64;
        const __nv_bfloat16* Bg = Bt + (size_t)n0 * K + (size_t)c * 64;
#pragma unroll
        for (int i = 0; i < 4; i++) {
            const int u = tid + 256 * i;
            const int row = u >> 3;
            const int seg = u & 7;
            const uint32_t so = (uint32_t)(row * KSW + seg * 4) * 4u;
            cp_async16(saw[b] + so, Ag + (size_t)row * K + seg * 8);
            cp_async16(sbw[b] + so, Bg + (size_t)row * K + seg * 8);
        }
        CP_COMMIT();
    };

    issue(0, 0);
    issue(1, 1);

    for (int c = 0; c < NCH; c++) {
        const int b = c & 1;
        CP_WAIT1();
        __syncthreads();
#pragma unroll
        for (int s = 0; s < 4; s++) {
            const uint32_t ks = (uint32_t)s * 32u;
            uint32_t af0[4], af1[4];
            ldsm_x4(af0, saw[b] + aoff0 + ks);
            ldsm_x4(af1, saw[b] + aoff1 + ks);
#pragma unroll
            for (int ntp = 0; ntp < 4; ntp++) {
                uint32_t bq[4];
                ldsm_x4(bq, sbw[b] + boff[ntp] + ks);
                mma_bf16(acc[0][2 * ntp],     af0, bq);
                mma_bf16(acc[1][2 * ntp],     af1, bq);
                mma_bf16(acc[0][2 * ntp + 1], af0, bq + 2);
                mma_bf16(acc[1][2 * ntp + 1], af1, bq + 2);
            }
        }
        __syncthreads();
        if (c + 2 < NCH) issue(c + 2, b);
        else CP_COMMIT();
    }

#pragma unroll
    for (int mt = 0; mt < 2; mt++) {
        const int r = m0 + mb + mt * 16 + g;
#pragma unroll
        for (int nt = 0; nt < 8; nt++) {
            const int cx = n0 + nb + nt * 8 + 2 * t;
            const float b0 = __ldg(&bias[cx]);
            const float b1 = __ldg(&bias[cx + 1]);
            float2 v0, v1;
            v0.x = acc[mt][nt][0] + b0; v0.y = acc[mt][nt][1] + b1;
            v1.x = acc[mt][nt][2] + b0; v1.y = acc[mt][nt][3] + b1;
            *(float2*)(C + (size_t)r * N + cx) = v0;
            *(float2*)(C + (size_t)(r + 8) * N + cx) = v1;
        }
    }
}

// ---------------------------------------------------------------------------
// bf16 HMMA flash attention with ldmatrix fragment loads.
// Q,K bf16 [32][2048][64]; VT bf16 [32][64][2048].
// CTA: 128 Q rows x 1 group, 8 warps (16 rows each), K-tiles of 64 keys,
// cp.async double-buffered.
// ---------------------------------------------------------------------------
#define AKW 36

__global__ __launch_bounds__(256) void attn_bf16(
    const __nv_bfloat16* __restrict__ Q, const __nv_bfloat16* __restrict__ K,
    const __nv_bfloat16* __restrict__ VT, const unsigned char* __restrict__ mask,
    __nv_bfloat16* __restrict__ O)
{
    extern __shared__ uint32_t smw[];
    uint32_t* sK[2]  = { smw,                smw + 64 * AKW };
    uint32_t* sVT[2] = { smw + 2 * 64 * AKW, smw + 3 * 64 * AKW };
    uint32_t* sP     = smw + 4 * 64 * AKW;   // [128][AKW]

    const int tid = threadIdx.x;
    const int wid = tid >> 5;
    const int lane = tid & 31;
    const int gq = lane >> 2;
    const int t = lane & 3;
    const int qb = blockIdx.x;
    const int grp = blockIdx.y;
    const int r0 = wid * 16;

    const int quad = lane >> 3;
    const int within = lane & 7;
    const int arow = (quad & 1) * 8 + within;
    const int acol = (quad >> 1) * 4;
    const int brow = (quad >> 1) * 8 + within;
    const int bcol = (quad & 1) * 4;

    uint32_t boffA[4];
#pragma unroll
    for (int ntp = 0; ntp < 4; ntp++)
        boffA[ntp] = (uint32_t)((ntp * 16 + brow) * AKW + bcol) * 4u;

    const uint32_t skw[2] = { smem_u32(sK[0]), smem_u32(sK[1]) };
    const uint32_t svw[2] = { smem_u32(sVT[0]), smem_u32(sVT[1]) };

    const __nv_bfloat16* Qg = Q + ((size_t)grp * SLEN + qb * 128 + r0) * HEADDIM;
    const __nv_bfloat16* Kg = K + (size_t)grp * SLEN * HEADDIM;
    const __nv_bfloat16* VTg = VT + (size_t)grp * SLEN * HEADDIM;
    const unsigned char* mrow =
        mask + (size_t)(grp % BATCH) * SLEN * SLEN + (size_t)(qb * 128 + r0) * SLEN;

    auto issue = [&](int kt, int b) {
#pragma unroll
        for (int i = 0; i < 2; i++) {
            const int u = tid + 256 * i;
            const int row = u >> 3;
            const int seg = u & 7;
            const uint32_t so = (uint32_t)(row * AKW + seg * 4) * 4u;
            cp_async16(skw[b] + so, Kg + (size_t)(kt * 64 + row) * HEADDIM + seg * 8);
            cp_async16(svw[b] + so, VTg + (size_t)row * SLEN + kt * 64 + seg * 8);
        }
        CP_COMMIT();
    };

    // ---- Stage Q (warp-private rows of sP), build persistent A fragments
    uint32_t* sQw = sP + r0 * AKW;
    const uint32_t spw_addr = smem_u32(sQw) + (uint32_t)(arow * AKW + acol) * 4u;
    {
        const int row = lane >> 1;
        const int cs = (lane & 1) * 16;
#pragma unroll
        for (int j = 0; j < 4; j++) {
            uint4 v = *(const uint4*)(Qg + (size_t)row * HEADDIM + (cs + j * 4) * 2);
            *(uint4*)&sQw[row * AKW + cs + j * 4] = v;
        }
    }
    __syncwarp();
    uint32_t qf[4][4];
#pragma unroll
    for (int s = 0; s < 4; s++)
        ldsm_x4(qf[s], spw_addr + (uint32_t)s * 32u);
    __syncthreads();   // Q fragments captured before sP reused for P

    issue(0, 0);
    issue(1, 1);

    float oacc[8][4];
#pragma unroll
    for (int nt = 0; nt < 8; nt++)
#pragma unroll
        for (int q = 0; q < 4; q++) oacc[nt][q] = 0.f;
    float mA = -INFINITY, mB = -INFINITY, lA = 0.f, lB = 0.f;

    const float scale = 0.125f;
    uint32_t* sPw = sP + r0 * AKW;
    const int NT = SLEN / 64;

    for (int kt = 0; kt < NT; kt++) {
        const int b = kt & 1;
        CP_WAIT1();
        __syncthreads();

        // ---- S = Q K^T (4 k-steps of 16; B via ldmatrix, 2 n-tiles per load)
        float sacc[8][4];
#pragma unroll
        for (int nt = 0; nt < 8; nt++)
#pragma unroll
            for (int q = 0; q < 4; q++) sacc[nt][q] = 0.f;
#pragma unroll
        for (int s = 0; s < 4; s++) {
            const uint32_t ks = (uint32_t)s * 32u;
#pragma unroll
            for (int ntp = 0; ntp < 4; ntp++) {
                uint32_t bq[4];
                ldsm_x4(bq, skw[b] + boffA[ntp] + ks);
                mma_bf16(sacc[2 * ntp],     qf[s], bq);
                mma_bf16(sacc[2 * ntp + 1], qf[s], bq + 2);
            }
        }

        // ---- Mask + scale
#pragma unroll
        for (int nt = 0; nt < 8; nt++) {
            const int cb = kt * 64 + nt * 8 + 2 * t;
            uchar2 ma = *(const uchar2*)(mrow + (size_t)gq * SLEN + cb);
            uchar2 mb2 = *(const uchar2*)(mrow + (size_t)(gq + 8) * SLEN + cb);
            sacc[nt][0] = ma.x ? -1e9f : sacc[nt][0] * scale;
            sacc[nt][1] = ma.y ? -1e9f : sacc[nt][1] * scale;
            sacc[nt][2] = mb2.x ? -1e9f : sacc[nt][2] * scale;
            sacc[nt][3] = mb2.y ? -1e9f : sacc[nt][3] * scale;
        }

        // ---- Online softmax
        float mxA = -INFINITY, mxB = -INFINITY;
#pragma unroll
        for (int nt = 0; nt < 8; nt++) {
            mxA = fmaxf(mxA, fmaxf(sacc[nt][0], sacc[nt][1]));
            mxB = fmaxf(mxB, fmaxf(sacc[nt][2], sacc[nt][3]));
        }
        mxA = fmaxf(mxA, __shfl_xor_sync(0xffffffffu, mxA, 1));
        mxA = fmaxf(mxA, __shfl_xor_sync(0xffffffffu, mxA, 2));
        mxB = fmaxf(mxB, __shfl_xor_sync(0xffffffffu, mxB, 1));
        mxB = fmaxf(mxB, __shfl_xor_sync(0xffffffffu, mxB, 2));

        const float mnA = fmaxf(mA, mxA);
        const float mnB = fmaxf(mB, mxB);
        const float cA = __expf(mA - mnA);
        const float cB = __expf(mB - mnB);
        float suA = 0.f, suB = 0.f;
#pragma unroll
        for (int nt = 0; nt < 8; nt++) {
            sacc[nt][0] = __expf(sacc[nt][0] - mnA);
            sacc[nt][1] = __expf(sacc[nt][1] - mnA);
            sacc[nt][2] = __expf(sacc[nt][2] - mnB);
            sacc[nt][3] = __expf(sacc[nt][3] - mnB);
            suA += sacc[nt][0] + sacc[nt][1];
            suB += sacc[nt][2] + sacc[nt][3];
        }
        suA += __shfl_xor_sync(0xffffffffu, suA, 1);
        suA += __shfl_xor_sync(0xffffffffu, suA, 2);
        suB += __shfl_xor_sync(0xffffffffu, suB, 1);
        suB += __shfl_xor_sync(0xffffffffu, suB, 2);
        lA = lA * cA + suA;
        lB = lB * cB + suB;
        mA = mnA;
        mB = mnB;
#pragma unroll
        for (int nt = 0; nt < 8; nt++) {
            oacc[nt][0] *= cA; oacc[nt][1] *= cA;
            oacc[nt][2] *= cB; oacc[nt][3] *= cB;
        }

        // ---- Stage P packed bf16x2 (warp-private rows)
#pragma unroll
        for (int nt = 0; nt < 8; nt++) {
            sPw[gq * AKW + nt * 4 + t]       = pack_bf16x2(sacc[nt][0], sacc[nt][1]);
            sPw[(gq + 8) * AKW + nt * 4 + t] = pack_bf16x2(sacc[nt][2], sacc[nt][3]);
        }
        __syncwarp();

        // ---- O += P V (A=P via ldmatrix, B=VT via ldmatrix)
#pragma unroll
        for (int s = 0; s < 4; s++) {
            const uint32_t ks = (uint32_t)s * 32u;
            uint32_t af[4];
            ldsm_x4(af, spw_addr + ks);
#pragma unroll
            for (int ntp = 0; ntp < 4; ntp++) {
                uint32_t bq[4];
                ldsm_x4(bq, svw[b] + boffA[ntp] + ks);
                mma_bf16(oacc[2 * ntp],     af, bq);
                mma_bf16(oacc[2 * ntp + 1], af, bq + 2);
            }
        }
        __syncthreads();
        if (kt + 2 < NT) issue(kt + 2, b);
        else CP_COMMIT();
    }

    // ---- Normalize + write O as bf16
    const float iA = 1.f / lA;
    const float iB = 1.f / lB;
    __nv_bfloat16* Og = O + ((size_t)grp * SLEN + qb * 128 + r0) * HEADDIM;
#pragma unroll
    for (int nt = 0; nt < 8; nt++) {
        const int cb = nt * 8 + 2 * t;
        uint32_t wA = pack_bf16x2(oacc[nt][0] * iA, oacc[nt][1] * iA);
        uint32_t wB = pack_bf16x2(oacc[nt][2] * iB, oacc[nt][3] * iB);
        *reinterpret_cast<uint32_t*>(Og + (size_t)gq * HEADDIM + cb) = wA;
        *reinterpret_cast<uint32_t*>(Og + (size_t)(gq + 8) * HEADDIM + cb) = wB;
    }
}

// ---------------------------------------------------------------------------
// Fused residual + LayerNorm (unchanged)
// ---------------------------------------------------------------------------
__global__ __launch_bounds__(256) void ln_kernel(
    const float* __restrict__ x, const float* __restrict__ p,
    const float* __restrict__ gamma, const float* __restrict__ beta,
    float* __restrict__ out)
{
    const int row = blockIdx.x;
    const int t = threadIdx.x;
    const size_t base = (size_t)row * DMODEL + t * 4;

    float4 xv = *(const float4*)(x + base);
    float4 pv = *(const float4*)(p + base);
    float v0 = xv.x + pv.x, v1 = xv.y + pv.y, v2 = xv.z + pv.z, v3 = xv.w + pv.w;

    __shared__ float red[8];
    float s = v0 + v1 + v2 + v3;
#pragma unroll
    for (int off = 16; off >= 1; off >>= 1) s += __shfl_xor_sync(0xffffffffu, s, off);
    if ((t & 31) == 0) red[t >> 5] = s;
    __syncthreads();
    float mu = (red[0] + red[1] + red[2] + red[3] +
                red[4] + red[5] + red[6] + red[7]) * (1.f / DMODEL);
    __syncthreads();

    float d0 = v0 - mu, d1 = v1 - mu, d2 = v2 - mu, d3 = v3 - mu;
    float q = d0 * d0 + d1 * d1 + d2 * d2 + d3 * d3;
#pragma unroll
    for (int off = 16; off >= 1; off >>= 1) q += __shfl_xor_sync(0xffffffffu, q, off);
    if ((t & 31) == 0) red[t >> 5] = q;
    __syncthreads();
    float var = (red[0] + red[1] + red[2] + red[3] +
                 red[4] + red[5] + red[6] + red[7]) * (1.f / DMODEL);
    float rs = rsqrtf(var + 1e-5f);

    float4 gv = *(const float4*)(gamma + t * 4);
    float4 bv = *(const float4*)(beta + t * 4);
    float4 ov;
    ov.x = d0 * rs * gv.x + bv.x;
    ov.y = d1 * rs * gv.y + bv.y;
    ov.z = d2 * rs * gv.z + bv.z;
    ov.w = d3 * rs * gv.w + bv.w;
    *(float4*)(out + base) = ov;
}

// ---------------------------------------------------------------------------
// Launch
// ---------------------------------------------------------------------------
extern "C" void kernel_launch(void* const* d_in, const int* in_sizes, int n_in,
                              void* d_out, int out_size)
{
    (void)in_sizes; (void)n_in; (void)out_size;
    const float* q_in  = (const float*)d_in[0];
    const float* k_in  = (const float*)d_in[1];
    const float* v_in  = (const float*)d_in[2];
    const unsigned char* mask = (const unsigned char*)d_in[3];
    const float* Wq = (const float*)d_in[4];
    const float* Wk = (const float*)d_in[5];
    const float* Wv = (const float*)d_in[6];
    const float* Wo = (const float*)d_in[7];
    const float* bo = (const float*)d_in[8];
    const float* gamma = (const float*)d_in[9];
    const float* beta  = (const float*)d_in[10];
    float* out = (float*)d_out;

    float* pP;
    __nv_bfloat16 *pQb, *pKb, *pVb, *pVTb, *pOb, *pQin, *pKin, *pVin;
    __nv_bfloat16 *pWqT, *pWkT, *pWvT, *pWoT;
    cudaGetSymbolAddress((void**)&pP, g_P);
    cudaGetSymbolAddress((void**)&pQb, g_Qb);
    cudaGetSymbolAddress((void**)&pKb, g_Kb);
    cudaGetSymbolAddress((void**)&pVb, g_Vb);
    cudaGetSymbolAddress((void**)&pVTb, g_VTb);
    cudaGetSymbolAddress((void**)&pOb, g_Ob);
    cudaGetSymbolAddress((void**)&pQin, g_Qin);
    cudaGetSymbolAddress((void**)&pKin, g_Kin);
    cudaGetSymbolAddress((void**)&pVin, g_Vin);
    cudaGetSymbolAddress((void**)&pWqT, g_WqT);
    cudaGetSymbolAddress((void**)&pWkT, g_WkT);
    cudaGetSymbolAddress((void**)&pWvT, g_WvT);
    cudaGetSymbolAddress((void**)&pWoT, g_WoT);

    const int gemm_smem = 4 * TILE_WORDS * (int)sizeof(uint32_t);   // 73728 B
    cudaFuncSetAttribute(gemm_bf16_qkv, cudaFuncAttributeMaxDynamicSharedMemorySize, gemm_smem);
    cudaFuncSetAttribute(gemm_bf16_out, cudaFuncAttributeMaxDynamicSharedMemorySize, gemm_smem);
    const int attn_smem = (4 * 64 * AKW + 128 * AKW) * (int)sizeof(uint32_t);  // 55296 B
    cudaFuncSetAttribute(attn_bf16, cudaFuncAttributeMaxDynamicSharedMemorySize, attn_smem);

    // fp32 -> bf16 input copies
    const int cvt_blocks = NROWS * DMODEL / (256 * 8);
    cvt_bf16<<<cvt_blocks, 256>>>(q_in, pQin);
    cvt_bf16<<<cvt_blocks, 256>>>(k_in, pKin);
    cvt_bf16<<<cvt_blocks, 256>>>(v_in, pVin);

    // transpose weights to [N, K] bf16
    dim3 tgrid(DMODEL / 32, DMODEL / 32);
    dim3 tblk(32, 8);
    transpose1024_bf16<<<tgrid, tblk>>>(Wq, pWqT);
    transpose1024_bf16<<<tgrid, tblk>>>(Wk, pWkT);
    transpose1024_bf16<<<tgrid, tblk>>>(Wv, pWvT);
    transpose1024_bf16<<<tgrid, tblk>>>(Wo, pWoT);

    // batched Q/K/V projections (bf16 out)
    dim3 ggrid3(DMODEL / 128, NROWS / 128, 3);
    gemm_bf16_qkv<<<ggrid3, 256, gemm_smem>>>(
        pQin, pKin, pVin, pWqT, pWkT, pWvT, pQb, pKb, pVb,
        NROWS, DMODEL, DMODEL);

    // V -> VT per group (bf16)
    dim3 vgrid(SLEN / 32, HEADDIM / 32, NGROUPS);
    vtranspose_bf16<<<vgrid, tblk>>>(pVb, pVTb);

    dim3 agrid(SLEN / 128, NGROUPS);
    attn_bf16<<<agrid, 256, attn_smem>>>(pQb, pKb, pVTb, mask, pOb);

    // output projection (+bias, fp32 out)
    dim3 ggrid1(DMODEL / 128, NROWS / 128);
    gemm_bf16_out<<<ggrid1, 256, gemm_smem>>>(pOb, pWoT, bo, pP, NROWS, DMODEL, DMODEL);

    ln_kernel<<<NROWS, 256>>>(q_in, pP, gamma, beta, out);
}